// round 1
// baseline (speedup 1.0000x reference)
#include <cuda_runtime.h>
#include <math.h>

// Problem constants
#define BB  2
#define TT  2048
#define CC  1024
#define HH  16
#define DD  64
#define N3  (3*CC)      // 3072
#define MM  (BB*TT)     // 4096

// Scratch for Q,K,V in [B,H,T,D] layout (device globals: allocation-free)
__device__ float g_q[BB*HH*TT*DD];
__device__ float g_k[BB*HH*TT*DD];
__device__ float g_v[BB*HH*TT*DD];

// ---------------------------------------------------------------------------
// Kernel 1: QKV = x @ w + b, scattered into g_q/g_k/g_v as [B,H,T,D]
// 128x128 tile, BK=16, 256 threads, 8x8 per-thread microtile.
// ---------------------------------------------------------------------------
__global__ __launch_bounds__(256)
void qkv_gemm(const float* __restrict__ x,
              const float* __restrict__ w,
              const float* __restrict__ bias)
{
    __shared__ float As[16][128];   // A stored transposed: As[k][m]
    __shared__ float Bs[16][128];   // Bs[k][n]

    const int n0  = blockIdx.x * 128;
    const int m0  = blockIdx.y * 128;
    const int tid = threadIdx.x;
    const int tm  = tid & 15;       // m microtile index
    const int tn  = tid >> 4;       // n microtile index

    // load-index decomposition
    const int a_m = tid >> 2;           // 0..63
    const int a_k = (tid & 3) << 2;     // 0,4,8,12
    const int b_k = tid >> 5;           // 0..7
    const int b_n = (tid & 31) << 2;    // 0..124

    float acc[8][8];
    #pragma unroll
    for (int i = 0; i < 8; i++)
        #pragma unroll
        for (int j = 0; j < 8; j++) acc[i][j] = 0.f;

    for (int k0 = 0; k0 < CC; k0 += 16) {
        #pragma unroll
        for (int hh = 0; hh < 2; hh++) {
            int m = a_m + hh * 64;
            float4 v = *(const float4*)(x + (size_t)(m0 + m) * CC + k0 + a_k);
            As[a_k + 0][m] = v.x;
            As[a_k + 1][m] = v.y;
            As[a_k + 2][m] = v.z;
            As[a_k + 3][m] = v.w;
        }
        #pragma unroll
        for (int hh = 0; hh < 2; hh++) {
            int k = b_k + hh * 8;
            *(float4*)&Bs[k][b_n] =
                *(const float4*)(w + (size_t)(k0 + k) * N3 + n0 + b_n);
        }
        __syncthreads();

        #pragma unroll
        for (int kk = 0; kk < 16; kk++) {
            float a[8], bf[8];
            *(float4*)&a[0]  = *(float4*)&As[kk][tm * 8];
            *(float4*)&a[4]  = *(float4*)&As[kk][tm * 8 + 4];
            *(float4*)&bf[0] = *(float4*)&Bs[kk][tn * 8];
            *(float4*)&bf[4] = *(float4*)&Bs[kk][tn * 8 + 4];
            #pragma unroll
            for (int i = 0; i < 8; i++)
                #pragma unroll
                for (int j = 0; j < 8; j++)
                    acc[i][j] += a[i] * bf[j];
        }
        __syncthreads();
    }

    // Epilogue: +bias, scatter to q/k/v in [B,H,T,D]
    #pragma unroll
    for (int i = 0; i < 8; i++) {
        int gm = m0 + tm * 8 + i;
        int b  = gm >> 11;          // / TT
        int t  = gm & (TT - 1);
        #pragma unroll
        for (int j = 0; j < 8; j += 4) {
            int gn = n0 + tn * 8 + j;
            int which = gn >> 10;   // / CC
            int c  = gn & (CC - 1);
            int h  = c >> 6;
            int d  = c & 63;
            float* dst = (which == 0) ? g_q : ((which == 1) ? g_k : g_v);
            float4 bv = *(const float4*)(bias + gn);
            float4 v;
            v.x = acc[i][j + 0] + bv.x;
            v.y = acc[i][j + 1] + bv.y;
            v.z = acc[i][j + 2] + bv.z;
            v.w = acc[i][j + 3] + bv.w;
            *(float4*)&dst[(((size_t)(b * HH + h) * TT + t) * DD + d)] = v;
        }
    }
}

// ---------------------------------------------------------------------------
// Kernel 2: causal flash attention, fp32. BM=BN=64, 256 threads, 4x4 tiles.
// Grid: (T/64, H, B). Output written directly as [B,T,C].
// ---------------------------------------------------------------------------
__global__ __launch_bounds__(256)
void attn(float* __restrict__ out)
{
    extern __shared__ float sm[];
    float* Qt  = sm;               // [64][64]  Qt[d][r], pre-scaled
    float* Kt  = Qt + 64 * 64;     // [64][64]  Kt[d][c]
    float* Vs  = Kt + 64 * 64;     // [64][64]  Vs[c][d]
    float* St  = Vs + 64 * 64;     // [64][68]  St[c][r] (pitch 68 for 16B align)
    float* m_s = St + 64 * 68;     // [64]
    float* l_s = m_s + 64;         // [64]
    float* f_s = l_s + 64;         // [64] rescale factor

    const int qi  = blockIdx.x;
    const int h   = blockIdx.y;
    const int b   = blockIdx.z;
    const int tid = threadIdx.x;
    const int tr  = tid & 15;      // row microtile
    const int tc  = tid >> 4;      // col microtile
    const size_t base = (size_t)(b * HH + h) * TT * DD;
    const int q0 = qi * 64;

    // Load Q tile, transposed + scaled
    {
        const float qscale = 0.125f;   // 1/sqrt(64)
        const float* gq = g_q + base + (size_t)q0 * DD;
        int r   = tid >> 2;
        int d4b = (tid & 3) * 4;
        #pragma unroll
        for (int p = 0; p < 4; p++) {
            int d4 = d4b + p * 16;
            float4 v = *(const float4*)(gq + r * 64 + d4);
            Qt[(d4 + 0) * 64 + r] = v.x * qscale;
            Qt[(d4 + 1) * 64 + r] = v.y * qscale;
            Qt[(d4 + 2) * 64 + r] = v.z * qscale;
            Qt[(d4 + 3) * 64 + r] = v.w * qscale;
        }
    }
    if (tid < 64) { m_s[tid] = -1e30f; l_s[tid] = 0.f; }

    float acc[4][4] = {};

    for (int j = 0; j <= qi; j++) {
        __syncthreads();   // previous iter done reading St/Vs; Q/m/l visible

        // Load K tile (transposed) and V tile (row-major copy)
        {
            const float* gk = g_k + base + (size_t)j * 64 * DD;
            int r   = tid >> 2;
            int d4b = (tid & 3) * 4;
            #pragma unroll
            for (int p = 0; p < 4; p++) {
                int d4 = d4b + p * 16;
                float4 v = *(const float4*)(gk + r * 64 + d4);
                Kt[(d4 + 0) * 64 + r] = v.x;
                Kt[(d4 + 1) * 64 + r] = v.y;
                Kt[(d4 + 2) * 64 + r] = v.z;
                Kt[(d4 + 3) * 64 + r] = v.w;
            }
            const float* gv = g_v + base + (size_t)j * 64 * DD;
            #pragma unroll
            for (int p = 0; p < 4; p++)
                *(float4*)&Vs[tid * 4 + p * 1024] =
                    *(const float4*)(gv + tid * 4 + p * 1024);
        }
        __syncthreads();

        // S[r][c] = sum_d Qt[d][r] * Kt[d][c]
        float s[4][4] = {};
        #pragma unroll 16
        for (int d = 0; d < 64; d++) {
            float4 qa = *(float4*)&Qt[d * 64 + tr * 4];
            float4 kb = *(float4*)&Kt[d * 64 + tc * 4];
            s[0][0] += qa.x * kb.x; s[0][1] += qa.x * kb.y;
            s[0][2] += qa.x * kb.z; s[0][3] += qa.x * kb.w;
            s[1][0] += qa.y * kb.x; s[1][1] += qa.y * kb.y;
            s[1][2] += qa.y * kb.z; s[1][3] += qa.y * kb.w;
            s[2][0] += qa.z * kb.x; s[2][1] += qa.z * kb.y;
            s[2][2] += qa.z * kb.z; s[2][3] += qa.z * kb.w;
            s[3][0] += qa.w * kb.x; s[3][1] += qa.w * kb.y;
            s[3][2] += qa.w * kb.z; s[3][3] += qa.w * kb.w;
        }
        // Causal mask + store transposed St[c][r]
        #pragma unroll
        for (int jj = 0; jj < 4; jj++) {
            int kg = j * 64 + tc * 4 + jj;
            float4 wv;
            wv.x = (kg <= q0 + tr * 4 + 0) ? s[0][jj] : -1e30f;
            wv.y = (kg <= q0 + tr * 4 + 1) ? s[1][jj] : -1e30f;
            wv.z = (kg <= q0 + tr * 4 + 2) ? s[2][jj] : -1e30f;
            wv.w = (kg <= q0 + tr * 4 + 3) ? s[3][jj] : -1e30f;
            *(float4*)&St[(tc * 4 + jj) * 68 + tr * 4] = wv;
        }
        __syncthreads();

        // Online softmax: 4 threads per row
        {
            int row  = tid >> 2;
            int part = tid & 3;
            float mold = m_s[row];
            float mx = -1e30f;
            #pragma unroll
            for (int cc = 0; cc < 16; cc++)
                mx = fmaxf(mx, St[(part + cc * 4) * 68 + row]);
            mx = fmaxf(mx, __shfl_xor_sync(0xffffffffu, mx, 1));
            mx = fmaxf(mx, __shfl_xor_sync(0xffffffffu, mx, 2));
            float mnew = fmaxf(mold, mx);
            float sum = 0.f;
            #pragma unroll
            for (int cc = 0; cc < 16; cc++) {
                int idx = (part + cc * 4) * 68 + row;
                float p = __expf(St[idx] - mnew);
                St[idx] = p;
                sum += p;
            }
            sum += __shfl_xor_sync(0xffffffffu, sum, 1);
            sum += __shfl_xor_sync(0xffffffffu, sum, 2);
            if (part == 0) {
                float f = __expf(mold - mnew);
                f_s[row] = f;
                m_s[row] = mnew;
                l_s[row] = l_s[row] * f + sum;
            }
        }
        __syncthreads();

        // Rescale accumulators and add P @ V
        #pragma unroll
        for (int i = 0; i < 4; i++) {
            float f = f_s[tr * 4 + i];
            acc[i][0] *= f; acc[i][1] *= f; acc[i][2] *= f; acc[i][3] *= f;
        }
        #pragma unroll 16
        for (int c = 0; c < 64; c++) {
            float4 p = *(float4*)&St[c * 68 + tr * 4];
            float4 v = *(float4*)&Vs[c * 64 + tc * 4];
            acc[0][0] += p.x * v.x; acc[0][1] += p.x * v.y;
            acc[0][2] += p.x * v.z; acc[0][3] += p.x * v.w;
            acc[1][0] += p.y * v.x; acc[1][1] += p.y * v.y;
            acc[1][2] += p.y * v.z; acc[1][3] += p.y * v.w;
            acc[2][0] += p.z * v.x; acc[2][1] += p.z * v.y;
            acc[2][2] += p.z * v.z; acc[2][3] += p.z * v.w;
            acc[3][0] += p.w * v.x; acc[3][1] += p.w * v.y;
            acc[3][2] += p.w * v.z; acc[3][3] += p.w * v.w;
        }
    }

    // Final normalize + write out as [B, T, C]
    #pragma unroll
    for (int i = 0; i < 4; i++) {
        int r = tr * 4 + i;
        float inv = 1.0f / l_s[r];
        float4 v;
        v.x = acc[i][0] * inv;
        v.y = acc[i][1] * inv;
        v.z = acc[i][2] * inv;
        v.w = acc[i][3] * inv;
        size_t o = ((size_t)(b * TT + q0 + r)) * CC + h * 64 + tc * 4;
        *(float4*)&out[o] = v;
    }
}

// ---------------------------------------------------------------------------
extern "C" void kernel_launch(void* const* d_in, const int* in_sizes, int n_in,
                              void* d_out, int out_size)
{
    const float* x    = (const float*)d_in[0];   // [2,2048,1024]
    const float* w    = (const float*)d_in[1];   // [1024,3072]
    const float* bias = (const float*)d_in[2];   // [3072]
    float* out = (float*)d_out;                  // [2,2048,1024]

    const int attn_smem = (3 * 64 * 64 + 64 * 68 + 3 * 64) * (int)sizeof(float);
    cudaFuncSetAttribute((const void*)attn,
                         cudaFuncAttributeMaxDynamicSharedMemorySize, attn_smem);

    qkv_gemm<<<dim3(N3 / 128, MM / 128), 256>>>(x, w, bias);
    attn<<<dim3(TT / 64, HH, BB), 256, attn_smem>>>(out);
}

// round 3
// speedup vs baseline: 1.3951x; 1.3951x over previous
#include <cuda_runtime.h>
#include <cuda_bf16.h>
#include <cstdint>
#include <math.h>

// Problem constants
#define BB  2
#define TT  2048
#define CC  1024
#define HH  16
#define DD  64
#define N3  (3*CC)      // 3072
#define MM  (BB*TT)     // 4096

// Scratch for Q,K,V in [B,H,T,D] layout (device globals: allocation-free)
__device__ float g_q[BB*HH*TT*DD];
__device__ float g_k[BB*HH*TT*DD];
__device__ float g_v[BB*HH*TT*DD];

// ===========================================================================
// Portable PTX helpers (sm_80+; legal on plain compute_103 target)
// ===========================================================================
__device__ __forceinline__ uint32_t smem_u32(const void* p) {
    uint32_t a;
    asm("{ .reg .u64 t; cvta.to.shared.u64 t, %1; cvt.u32.u64 %0, t; }"
        : "=r"(a) : "l"(p));
    return a;
}

__device__ __forceinline__ void ldsm_x4(uint32_t& r0, uint32_t& r1,
                                        uint32_t& r2, uint32_t& r3,
                                        uint32_t addr) {
    asm volatile("ldmatrix.sync.aligned.m8n8.x4.shared.b16 {%0,%1,%2,%3}, [%4];"
                 : "=r"(r0), "=r"(r1), "=r"(r2), "=r"(r3) : "r"(addr));
}

__device__ __forceinline__ void mma_bf16(float* c,
                                         uint32_t a0, uint32_t a1,
                                         uint32_t a2, uint32_t a3,
                                         uint32_t b0, uint32_t b1) {
    asm volatile(
        "mma.sync.aligned.m16n8k16.row.col.f32.bf16.bf16.f32 "
        "{%0,%1,%2,%3}, {%4,%5,%6,%7}, {%8,%9}, {%0,%1,%2,%3};"
        : "+f"(c[0]), "+f"(c[1]), "+f"(c[2]), "+f"(c[3])
        : "r"(a0), "r"(a1), "r"(a2), "r"(a3), "r"(b0), "r"(b1));
}

// split fp32 -> (hi-bf16 pair, lo-bf16 pair) for 2 consecutive values
__device__ __forceinline__ void split2(float v0, float v1,
                                       uint32_t& h, uint32_t& l) {
    uint32_t u0 = __float_as_uint(v0), u1 = __float_as_uint(v1);
    h = __byte_perm(u0, u1, 0x7632);               // hi16(v1):hi16(v0)
    float l0 = v0 - __uint_as_float(u0 & 0xFFFF0000u);
    float l1 = v1 - __uint_as_float(u1 & 0xFFFF0000u);
    asm("cvt.rn.bf16x2.f32 %0, %1, %2;" : "=r"(l) : "f"(l1), "f"(l0));
}

// ===========================================================================
// Kernel 1: QKV = x @ w + b via mma.sync bf16x3 (split precision)
// CTA tile M=128 N=128, BK=32, 256 threads, double-buffered smem, prefetch.
// Smem bf16 tiles use 80-byte row pitch (conflict-free ldmatrix).
// ===========================================================================
#define TILE_BYTES 10240            // 128 rows * 80B
#define PITCH      80
#define OFF_STAGE  81920            // after 8 tiles (2 buf * 4 tiles)
#define STAGE_P    132              // fp32 stage pitch (words)
#define GEMM_SMEM  (OFF_STAGE + 32*STAGE_P*4)   // 98816

__global__ __launch_bounds__(256, 1)
void qkv_gemm_mma(const float* __restrict__ x,
                  const float* __restrict__ w,
                  const float* __restrict__ bias)
{
    extern __shared__ char smem[];
    const uint32_t sb = smem_u32(smem);
    float* stage = (float*)(smem + OFF_STAGE);

    const int tid = threadIdx.x;
    const int lid = tid & 31;
    const int wid = tid >> 5;
    const int wm  = wid & 3;        // M group: 4 x 32 rows
    const int wn  = wid >> 2;       // N group: 2 x 64 cols
    const int n0  = blockIdx.x * 128;
    const int m0  = blockIdx.y * 128;

    // per-thread load indices
    const int a_m  = tid >> 3;              // 0..31 (x4 passes -> 128 rows)
    const int a_k4 = tid & 7;               // float4 index along k (32 k)
    const int b_k  = tid >> 5;              // 0..7 (x4 passes -> 32 k rows)
    const int b_n4 = tid & 31;              // float4 index along n (128 n)
    // transpose-phase indices
    const int t_n  = tid & 127;
    const int t_kh = tid >> 7;              // 0/1 -> k half (16 each)

    // ldmatrix lane geometry
    const int a_r  = (lid & 7) + ((lid >> 3) & 1) * 8;
    const int a_cb = (lid >> 4) * 16;       // byte offset of k-quadrant
    const int b_r  = ((lid >> 4) & 1) * 8 + (lid & 7);
    const int b_cb = ((lid >> 3) & 1) * 16;

    float acc[2][8][4];
    #pragma unroll
    for (int i = 0; i < 2; i++)
        #pragma unroll
        for (int j = 0; j < 8; j++)
            #pragma unroll
            for (int q = 0; q < 4; q++) acc[i][j][q] = 0.f;

    const float* xp = x + (size_t)m0 * CC;
    const float* wp = w + n0;

    float4 ax[4], bx[4];

    // ---- helpers as lambdas ----
    auto load_regs = [&](int k0) {
        #pragma unroll
        for (int p = 0; p < 4; ++p) {
            int m = a_m + p * 32;
            ax[p] = *(const float4*)(xp + (size_t)m * CC + k0 + a_k4 * 4);
            int kk = b_k + p * 8;
            bx[p] = *(const float4*)(wp + (size_t)(k0 + kk) * N3 + b_n4 * 4);
        }
    };
    auto convertA_fillstage = [&](int buf) {
        char* Ah = smem + (buf * 4 + 0) * TILE_BYTES;
        char* Al = smem + (buf * 4 + 1) * TILE_BYTES;
        #pragma unroll
        for (int p = 0; p < 4; ++p) {
            int m = a_m + p * 32;
            uint32_t h01, l01, h23, l23;
            split2(ax[p].x, ax[p].y, h01, l01);
            split2(ax[p].z, ax[p].w, h23, l23);
            int off = m * PITCH + a_k4 * 8;
            *(uint2*)(Ah + off) = make_uint2(h01, h23);
            *(uint2*)(Al + off) = make_uint2(l01, l23);
            int kk = b_k + p * 8;
            *(float4*)(stage + kk * STAGE_P + b_n4 * 4) = bx[p];
        }
    };
    auto transposeB = [&](int buf) {
        char* Bh = smem + (buf * 4 + 2) * TILE_BYTES;
        char* Bl = smem + (buf * 4 + 3) * TILE_BYTES;
        const float* srow = stage + t_n;
        #pragma unroll
        for (int q = 0; q < 4; ++q) {
            int k = t_kh * 16 + q * 4;
            float a0 = srow[(k + 0) * STAGE_P];
            float a1 = srow[(k + 1) * STAGE_P];
            float a2 = srow[(k + 2) * STAGE_P];
            float a3 = srow[(k + 3) * STAGE_P];
            uint32_t h01, l01, h23, l23;
            split2(a0, a1, h01, l01);
            split2(a2, a3, h23, l23);
            int off = t_n * PITCH + k * 2;
            *(uint2*)(Bh + off) = make_uint2(h01, h23);
            *(uint2*)(Bl + off) = make_uint2(l01, l23);
        }
    };
    auto compute = [&](int buf) {
        const uint32_t Ah = sb + (buf * 4 + 0) * TILE_BYTES;
        const uint32_t Al = sb + (buf * 4 + 1) * TILE_BYTES;
        const uint32_t Bh = sb + (buf * 4 + 2) * TILE_BYTES;
        const uint32_t Bl = sb + (buf * 4 + 3) * TILE_BYTES;
        #pragma unroll
        for (int ks = 0; ks < 2; ++ks) {
            const int kb = ks * 32;  // byte offset along k (16 bf16)
            uint32_t ah[2][4], al[2][4], bh[4][4], bl[4][4];
            #pragma unroll
            for (int mt = 0; mt < 2; ++mt) {
                uint32_t ra = (wm * 32 + mt * 16 + a_r) * PITCH + a_cb + kb;
                ldsm_x4(ah[mt][0], ah[mt][1], ah[mt][2], ah[mt][3], Ah + ra);
                ldsm_x4(al[mt][0], al[mt][1], al[mt][2], al[mt][3], Al + ra);
            }
            #pragma unroll
            for (int bt = 0; bt < 4; ++bt) {
                uint32_t rb = (wn * 64 + bt * 16 + b_r) * PITCH + b_cb + kb;
                ldsm_x4(bh[bt][0], bh[bt][1], bh[bt][2], bh[bt][3], Bh + rb);
                ldsm_x4(bl[bt][0], bl[bt][1], bl[bt][2], bl[bt][3], Bl + rb);
            }
            #pragma unroll
            for (int mt = 0; mt < 2; ++mt)
                #pragma unroll
                for (int nt = 0; nt < 8; ++nt) {
                    uint32_t b0h = bh[nt >> 1][(nt & 1) * 2];
                    uint32_t b1h = bh[nt >> 1][(nt & 1) * 2 + 1];
                    uint32_t b0l = bl[nt >> 1][(nt & 1) * 2];
                    uint32_t b1l = bl[nt >> 1][(nt & 1) * 2 + 1];
                    mma_bf16(acc[mt][nt], ah[mt][0], ah[mt][1], ah[mt][2], ah[mt][3], b0h, b1h);
                    mma_bf16(acc[mt][nt], ah[mt][0], ah[mt][1], ah[mt][2], ah[mt][3], b0l, b1l);
                    mma_bf16(acc[mt][nt], al[mt][0], al[mt][1], al[mt][2], al[mt][3], b0h, b1h);
                }
        }
    };

    // ---- pipeline ----
    load_regs(0);
    convertA_fillstage(0);
    __syncthreads();
    transposeB(0);
    __syncthreads();

    for (int it = 0; it < 32; ++it) {
        if (it < 31) load_regs((it + 1) * 32);
        compute(it & 1);
        if (it < 31) {
            convertA_fillstage((it + 1) & 1);
            __syncthreads();
            transposeB((it + 1) & 1);
            __syncthreads();
        }
    }

    // ---- epilogue: +bias, scatter to g_q/g_k/g_v [B,H,T,D] ----
    {
        const int n_warp = n0 + wn * 64;       // 64-aligned
        const int which  = n_warp >> 10;
        const int ccn    = n_warp & (CC - 1);
        const int h      = ccn >> 6;
        float* dst = (which == 0) ? g_q : ((which == 1) ? g_k : g_v);

        #pragma unroll
        for (int mt = 0; mt < 2; ++mt) {
            int gm = m0 + wm * 32 + mt * 16 + (lid >> 2);
            #pragma unroll
            for (int half = 0; half < 2; ++half) {
                int gmr = gm + half * 8;
                int bb = gmr >> 11;
                int t  = gmr & (TT - 1);
                float* drow = dst + ((size_t)(bb * HH + h) * TT + t) * DD;
                #pragma unroll
                for (int nt = 0; nt < 8; ++nt) {
                    int d = nt * 8 + (lid & 3) * 2;
                    float2 bv = *(const float2*)(bias + n_warp + d);
                    float2 o;
                    o.x = acc[mt][nt][half * 2 + 0] + bv.x;
                    o.y = acc[mt][nt][half * 2 + 1] + bv.y;
                    *(float2*)(drow + d) = o;
                }
            }
        }
    }
}

// ---------------------------------------------------------------------------
// Kernel 2: causal flash attention, fp32. BM=BN=64, 256 threads, 4x4 tiles.
// (unchanged — passing at 633us; next optimization target)
// ---------------------------------------------------------------------------
__global__ __launch_bounds__(256)
void attn(float* __restrict__ out)
{
    extern __shared__ float sm[];
    float* Qt  = sm;               // [64][64]  Qt[d][r], pre-scaled
    float* Kt  = Qt + 64 * 64;     // [64][64]  Kt[d][c]
    float* Vs  = Kt + 64 * 64;     // [64][64]  Vs[c][d]
    float* St  = Vs + 64 * 64;     // [64][68]  St[c][r]
    float* m_s = St + 64 * 68;     // [64]
    float* l_s = m_s + 64;         // [64]
    float* f_s = l_s + 64;         // [64]

    const int qi  = blockIdx.x;
    const int h   = blockIdx.y;
    const int b   = blockIdx.z;
    const int tid = threadIdx.x;
    const int tr  = tid & 15;
    const int tc  = tid >> 4;
    const size_t base = (size_t)(b * HH + h) * TT * DD;
    const int q0 = qi * 64;

    {
        const float qscale = 0.125f;
        const float* gq = g_q + base + (size_t)q0 * DD;
        int r   = tid >> 2;
        int d4b = (tid & 3) * 4;
        #pragma unroll
        for (int p = 0; p < 4; p++) {
            int d4 = d4b + p * 16;
            float4 v = *(const float4*)(gq + r * 64 + d4);
            Qt[(d4 + 0) * 64 + r] = v.x * qscale;
            Qt[(d4 + 1) * 64 + r] = v.y * qscale;
            Qt[(d4 + 2) * 64 + r] = v.z * qscale;
            Qt[(d4 + 3) * 64 + r] = v.w * qscale;
        }
    }
    if (tid < 64) { m_s[tid] = -1e30f; l_s[tid] = 0.f; }

    float acc[4][4] = {};

    for (int j = 0; j <= qi; j++) {
        __syncthreads();
        {
            const float* gk = g_k + base + (size_t)j * 64 * DD;
            int r   = tid >> 2;
            int d4b = (tid & 3) * 4;
            #pragma unroll
            for (int p = 0; p < 4; p++) {
                int d4 = d4b + p * 16;
                float4 v = *(const float4*)(gk + r * 64 + d4);
                Kt[(d4 + 0) * 64 + r] = v.x;
                Kt[(d4 + 1) * 64 + r] = v.y;
                Kt[(d4 + 2) * 64 + r] = v.z;
                Kt[(d4 + 3) * 64 + r] = v.w;
            }
            const float* gv = g_v + base + (size_t)j * 64 * DD;
            #pragma unroll
            for (int p = 0; p < 4; p++)
                *(float4*)&Vs[tid * 4 + p * 1024] =
                    *(const float4*)(gv + tid * 4 + p * 1024);
        }
        __syncthreads();

        float s[4][4] = {};
        #pragma unroll 16
        for (int d = 0; d < 64; d++) {
            float4 qa = *(float4*)&Qt[d * 64 + tr * 4];
            float4 kb = *(float4*)&Kt[d * 64 + tc * 4];
            s[0][0] += qa.x * kb.x; s[0][1] += qa.x * kb.y;
            s[0][2] += qa.x * kb.z; s[0][3] += qa.x * kb.w;
            s[1][0] += qa.y * kb.x; s[1][1] += qa.y * kb.y;
            s[1][2] += qa.y * kb.z; s[1][3] += qa.y * kb.w;
            s[2][0] += qa.z * kb.x; s[2][1] += qa.z * kb.y;
            s[2][2] += qa.z * kb.z; s[2][3] += qa.z * kb.w;
            s[3][0] += qa.w * kb.x; s[3][1] += qa.w * kb.y;
            s[3][2] += qa.w * kb.z; s[3][3] += qa.w * kb.w;
        }
        #pragma unroll
        for (int jj = 0; jj < 4; jj++) {
            int kg = j * 64 + tc * 4 + jj;
            float4 wv;
            wv.x = (kg <= q0 + tr * 4 + 0) ? s[0][jj] : -1e30f;
            wv.y = (kg <= q0 + tr * 4 + 1) ? s[1][jj] : -1e30f;
            wv.z = (kg <= q0 + tr * 4 + 2) ? s[2][jj] : -1e30f;
            wv.w = (kg <= q0 + tr * 4 + 3) ? s[3][jj] : -1e30f;
            *(float4*)&St[(tc * 4 + jj) * 68 + tr * 4] = wv;
        }
        __syncthreads();

        {
            int row  = tid >> 2;
            int part = tid & 3;
            float mold = m_s[row];
            float mx = -1e30f;
            #pragma unroll
            for (int cc = 0; cc < 16; cc++)
                mx = fmaxf(mx, St[(part + cc * 4) * 68 + row]);
            mx = fmaxf(mx, __shfl_xor_sync(0xffffffffu, mx, 1));
            mx = fmaxf(mx, __shfl_xor_sync(0xffffffffu, mx, 2));
            float mnew = fmaxf(mold, mx);
            float sum = 0.f;
            #pragma unroll
            for (int cc = 0; cc < 16; cc++) {
                int idx = (part + cc * 4) * 68 + row;
                float p = __expf(St[idx] - mnew);
                St[idx] = p;
                sum += p;
            }
            sum += __shfl_xor_sync(0xffffffffu, sum, 1);
            sum += __shfl_xor_sync(0xffffffffu, sum, 2);
            if (part == 0) {
                float f = __expf(mold - mnew);
                f_s[row] = f;
                m_s[row] = mnew;
                l_s[row] = l_s[row] * f + sum;
            }
        }
        __syncthreads();

        #pragma unroll
        for (int i = 0; i < 4; i++) {
            float f = f_s[tr * 4 + i];
            acc[i][0] *= f; acc[i][1] *= f; acc[i][2] *= f; acc[i][3] *= f;
        }
        #pragma unroll 16
        for (int c = 0; c < 64; c++) {
            float4 p = *(float4*)&St[c * 68 + tr * 4];
            float4 v = *(float4*)&Vs[c * 64 + tc * 4];
            acc[0][0] += p.x * v.x; acc[0][1] += p.x * v.y;
            acc[0][2] += p.x * v.z; acc[0][3] += p.x * v.w;
            acc[1][0] += p.y * v.x; acc[1][1] += p.y * v.y;
            acc[1][2] += p.y * v.z; acc[1][3] += p.y * v.w;
            acc[2][0] += p.z * v.x; acc[2][1] += p.z * v.y;
            acc[2][2] += p.z * v.z; acc[2][3] += p.z * v.w;
            acc[3][0] += p.w * v.x; acc[3][1] += p.w * v.y;
            acc[3][2] += p.w * v.z; acc[3][3] += p.w * v.w;
        }
    }

    #pragma unroll
    for (int i = 0; i < 4; i++) {
        int r = tr * 4 + i;
        float inv = 1.0f / l_s[r];
        float4 v;
        v.x = acc[i][0] * inv;
        v.y = acc[i][1] * inv;
        v.z = acc[i][2] * inv;
        v.w = acc[i][3] * inv;
        size_t o = ((size_t)(b * TT + q0 + r)) * CC + h * 64 + tc * 4;
        *(float4*)&out[o] = v;
    }
}

// ---------------------------------------------------------------------------
extern "C" void kernel_launch(void* const* d_in, const int* in_sizes, int n_in,
                              void* d_out, int out_size)
{
    const float* x    = (const float*)d_in[0];   // [2,2048,1024]
    const float* w    = (const float*)d_in[1];   // [1024,3072]
    const float* bias = (const float*)d_in[2];   // [3072]
    float* out = (float*)d_out;                  // [2,2048,1024]

    cudaFuncSetAttribute((const void*)qkv_gemm_mma,
                         cudaFuncAttributeMaxDynamicSharedMemorySize, GEMM_SMEM);
    const int attn_smem = (3 * 64 * 64 + 64 * 68 + 3 * 64) * (int)sizeof(float);
    cudaFuncSetAttribute((const void*)attn,
                         cudaFuncAttributeMaxDynamicSharedMemorySize, attn_smem);

    qkv_gemm_mma<<<dim3(N3 / 128, MM / 128), 256, GEMM_SMEM>>>(x, w, bias);
    attn<<<dim3(TT / 64, HH, BB), 256, attn_smem>>>(out);
}

// round 4
// speedup vs baseline: 2.5097x; 1.7989x over previous
#include <cuda_runtime.h>
#include <cuda_bf16.h>
#include <cstdint>
#include <math.h>

// Problem constants
#define BB  2
#define TT  2048
#define CC  1024
#define HH  16
#define DD  64
#define N3  (3*CC)      // 3072
#define MM  (BB*TT)     // 4096

// Scratch for Q,K,V in [B,H,T,D] layout (device globals: allocation-free)
__device__ float g_q[BB*HH*TT*DD];
__device__ float g_k[BB*HH*TT*DD];
__device__ float g_v[BB*HH*TT*DD];

// ===========================================================================
// Portable PTX helpers (sm_80+; legal on plain compute_103 target)
// ===========================================================================
__device__ __forceinline__ uint32_t smem_u32(const void* p) {
    uint32_t a;
    asm("{ .reg .u64 t; cvta.to.shared.u64 t, %1; cvt.u32.u64 %0, t; }"
        : "=r"(a) : "l"(p));
    return a;
}

__device__ __forceinline__ void ldsm_x4(uint32_t& r0, uint32_t& r1,
                                        uint32_t& r2, uint32_t& r3,
                                        uint32_t addr) {
    asm volatile("ldmatrix.sync.aligned.m8n8.x4.shared.b16 {%0,%1,%2,%3}, [%4];"
                 : "=r"(r0), "=r"(r1), "=r"(r2), "=r"(r3) : "r"(addr));
}

__device__ __forceinline__ void ldsm_x4_t(uint32_t& r0, uint32_t& r1,
                                          uint32_t& r2, uint32_t& r3,
                                          uint32_t addr) {
    asm volatile("ldmatrix.sync.aligned.m8n8.x4.trans.shared.b16 {%0,%1,%2,%3}, [%4];"
                 : "=r"(r0), "=r"(r1), "=r"(r2), "=r"(r3) : "r"(addr));
}

__device__ __forceinline__ void mma_bf16(float* c,
                                         uint32_t a0, uint32_t a1,
                                         uint32_t a2, uint32_t a3,
                                         uint32_t b0, uint32_t b1) {
    asm volatile(
        "mma.sync.aligned.m16n8k16.row.col.f32.bf16.bf16.f32 "
        "{%0,%1,%2,%3}, {%4,%5,%6,%7}, {%8,%9}, {%0,%1,%2,%3};"
        : "+f"(c[0]), "+f"(c[1]), "+f"(c[2]), "+f"(c[3])
        : "r"(a0), "r"(a1), "r"(a2), "r"(a3), "r"(b0), "r"(b1));
}

// split fp32 -> (hi-bf16 pair [trunc], lo-bf16 pair [residual]) for 2 values
__device__ __forceinline__ void split2(float v0, float v1,
                                       uint32_t& h, uint32_t& l) {
    uint32_t u0 = __float_as_uint(v0), u1 = __float_as_uint(v1);
    h = __byte_perm(u0, u1, 0x7632);               // hi16(v1):hi16(v0)
    float l0 = v0 - __uint_as_float(u0 & 0xFFFF0000u);
    float l1 = v1 - __uint_as_float(u1 & 0xFFFF0000u);
    asm("cvt.rn.bf16x2.f32 %0, %1, %2;" : "=r"(l) : "f"(l1), "f"(l0));
}

// split softmax prob pair -> rn-bf16 pack + residual pack
__device__ __forceinline__ void packP(float p0, float p1,
                                      uint32_t& hi, uint32_t& lo) {
    asm("cvt.rn.bf16x2.f32 %0, %1, %2;" : "=r"(hi) : "f"(p1), "f"(p0));
    float h0 = __uint_as_float(hi << 16);
    float h1 = __uint_as_float(hi & 0xFFFF0000u);
    float r0 = p0 - h0, r1 = p1 - h1;
    asm("cvt.rn.bf16x2.f32 %0, %1, %2;" : "=r"(lo) : "f"(r1), "f"(r0));
}

// ===========================================================================
// Kernel 1: QKV = x @ w + b via mma.sync bf16x3 (split precision)
// (unchanged from round 3 — ~243us)
// ===========================================================================
#define TILE_BYTES 10240            // 128 rows * 80B
#define PITCH      80
#define OFF_STAGE  81920            // after 8 tiles (2 buf * 4 tiles)
#define STAGE_P    132              // fp32 stage pitch (words)
#define GEMM_SMEM  (OFF_STAGE + 32*STAGE_P*4)   // 98816

__global__ __launch_bounds__(256, 1)
void qkv_gemm_mma(const float* __restrict__ x,
                  const float* __restrict__ w,
                  const float* __restrict__ bias)
{
    extern __shared__ char smem[];
    const uint32_t sb = smem_u32(smem);
    float* stage = (float*)(smem + OFF_STAGE);

    const int tid = threadIdx.x;
    const int lid = tid & 31;
    const int wid = tid >> 5;
    const int wm  = wid & 3;
    const int wn  = wid >> 2;
    const int n0  = blockIdx.x * 128;
    const int m0  = blockIdx.y * 128;

    const int a_m  = tid >> 3;
    const int a_k4 = tid & 7;
    const int b_k  = tid >> 5;
    const int b_n4 = tid & 31;
    const int t_n  = tid & 127;
    const int t_kh = tid >> 7;

    const int a_r  = (lid & 7) + ((lid >> 3) & 1) * 8;
    const int a_cb = (lid >> 4) * 16;
    const int b_r  = ((lid >> 4) & 1) * 8 + (lid & 7);
    const int b_cb = ((lid >> 3) & 1) * 16;

    float acc[2][8][4];
    #pragma unroll
    for (int i = 0; i < 2; i++)
        #pragma unroll
        for (int j = 0; j < 8; j++)
            #pragma unroll
            for (int q = 0; q < 4; q++) acc[i][j][q] = 0.f;

    const float* xp = x + (size_t)m0 * CC;
    const float* wp = w + n0;

    float4 ax[4], bx[4];

    auto load_regs = [&](int k0) {
        #pragma unroll
        for (int p = 0; p < 4; ++p) {
            int m = a_m + p * 32;
            ax[p] = *(const float4*)(xp + (size_t)m * CC + k0 + a_k4 * 4);
            int kk = b_k + p * 8;
            bx[p] = *(const float4*)(wp + (size_t)(k0 + kk) * N3 + b_n4 * 4);
        }
    };
    auto convertA_fillstage = [&](int buf) {
        char* Ah = smem + (buf * 4 + 0) * TILE_BYTES;
        char* Al = smem + (buf * 4 + 1) * TILE_BYTES;
        #pragma unroll
        for (int p = 0; p < 4; ++p) {
            int m = a_m + p * 32;
            uint32_t h01, l01, h23, l23;
            split2(ax[p].x, ax[p].y, h01, l01);
            split2(ax[p].z, ax[p].w, h23, l23);
            int off = m * PITCH + a_k4 * 8;
            *(uint2*)(Ah + off) = make_uint2(h01, h23);
            *(uint2*)(Al + off) = make_uint2(l01, l23);
            int kk = b_k + p * 8;
            *(float4*)(stage + kk * STAGE_P + b_n4 * 4) = bx[p];
        }
    };
    auto transposeB = [&](int buf) {
        char* Bh = smem + (buf * 4 + 2) * TILE_BYTES;
        char* Bl = smem + (buf * 4 + 3) * TILE_BYTES;
        const float* srow = stage + t_n;
        #pragma unroll
        for (int q = 0; q < 4; ++q) {
            int k = t_kh * 16 + q * 4;
            float a0 = srow[(k + 0) * STAGE_P];
            float a1 = srow[(k + 1) * STAGE_P];
            float a2 = srow[(k + 2) * STAGE_P];
            float a3 = srow[(k + 3) * STAGE_P];
            uint32_t h01, l01, h23, l23;
            split2(a0, a1, h01, l01);
            split2(a2, a3, h23, l23);
            int off = t_n * PITCH + k * 2;
            *(uint2*)(Bh + off) = make_uint2(h01, h23);
            *(uint2*)(Bl + off) = make_uint2(l01, l23);
        }
    };
    auto compute = [&](int buf) {
        const uint32_t Ah = sb + (buf * 4 + 0) * TILE_BYTES;
        const uint32_t Al = sb + (buf * 4 + 1) * TILE_BYTES;
        const uint32_t Bh = sb + (buf * 4 + 2) * TILE_BYTES;
        const uint32_t Bl = sb + (buf * 4 + 3) * TILE_BYTES;
        #pragma unroll
        for (int ks = 0; ks < 2; ++ks) {
            const int kb = ks * 32;
            uint32_t ah[2][4], al[2][4], bh[4][4], bl[4][4];
            #pragma unroll
            for (int mt = 0; mt < 2; ++mt) {
                uint32_t ra = (wm * 32 + mt * 16 + a_r) * PITCH + a_cb + kb;
                ldsm_x4(ah[mt][0], ah[mt][1], ah[mt][2], ah[mt][3], Ah + ra);
                ldsm_x4(al[mt][0], al[mt][1], al[mt][2], al[mt][3], Al + ra);
            }
            #pragma unroll
            for (int bt = 0; bt < 4; ++bt) {
                uint32_t rb = (wn * 64 + bt * 16 + b_r) * PITCH + b_cb + kb;
                ldsm_x4(bh[bt][0], bh[bt][1], bh[bt][2], bh[bt][3], Bh + rb);
                ldsm_x4(bl[bt][0], bl[bt][1], bl[bt][2], bl[bt][3], Bl + rb);
            }
            #pragma unroll
            for (int mt = 0; mt < 2; ++mt)
                #pragma unroll
                for (int nt = 0; nt < 8; ++nt) {
                    uint32_t b0h = bh[nt >> 1][(nt & 1) * 2];
                    uint32_t b1h = bh[nt >> 1][(nt & 1) * 2 + 1];
                    uint32_t b0l = bl[nt >> 1][(nt & 1) * 2];
                    uint32_t b1l = bl[nt >> 1][(nt & 1) * 2 + 1];
                    mma_bf16(acc[mt][nt], ah[mt][0], ah[mt][1], ah[mt][2], ah[mt][3], b0h, b1h);
                    mma_bf16(acc[mt][nt], ah[mt][0], ah[mt][1], ah[mt][2], ah[mt][3], b0l, b1l);
                    mma_bf16(acc[mt][nt], al[mt][0], al[mt][1], al[mt][2], al[mt][3], b0h, b1h);
                }
        }
    };

    load_regs(0);
    convertA_fillstage(0);
    __syncthreads();
    transposeB(0);
    __syncthreads();

    for (int it = 0; it < 32; ++it) {
        if (it < 31) load_regs((it + 1) * 32);
        compute(it & 1);
        if (it < 31) {
            convertA_fillstage((it + 1) & 1);
            __syncthreads();
            transposeB((it + 1) & 1);
            __syncthreads();
        }
    }

    {
        const int n_warp = n0 + wn * 64;
        const int which  = n_warp >> 10;
        const int ccn    = n_warp & (CC - 1);
        const int h      = ccn >> 6;
        float* dst = (which == 0) ? g_q : ((which == 1) ? g_k : g_v);

        #pragma unroll
        for (int mt = 0; mt < 2; ++mt) {
            int gm = m0 + wm * 32 + mt * 16 + (lid >> 2);
            #pragma unroll
            for (int half = 0; half < 2; ++half) {
                int gmr = gm + half * 8;
                int bb = gmr >> 11;
                int t  = gmr & (TT - 1);
                float* drow = dst + ((size_t)(bb * HH + h) * TT + t) * DD;
                #pragma unroll
                for (int nt = 0; nt < 8; ++nt) {
                    int d = nt * 8 + (lid & 3) * 2;
                    float2 bv = *(const float2*)(bias + n_warp + d);
                    float2 o;
                    o.x = acc[mt][nt][half * 2 + 0] + bv.x;
                    o.y = acc[mt][nt][half * 2 + 1] + bv.y;
                    *(float2*)(drow + d) = o;
                }
            }
        }
    }
}

// ===========================================================================
// Kernel 2: causal flash attention via mma.sync bf16 split precision.
// CTA: 128 q-rows (8 warps x 16), KV tiles of 64. Softmax in registers.
// Smem: Kh/Kl/Vh/Vl 64x64 bf16 tiles at 144B pitch (Q staged through same).
// ===========================================================================
#define APITCH   144
#define AT_KH    0
#define AT_KL    9216
#define AT_VH    18432
#define AT_VL    27648
#define ATTN_SMEM 36864

__global__ __launch_bounds__(256, 1)
void attn_mma(float* __restrict__ out)
{
    extern __shared__ char smem[];
    const uint32_t sb = smem_u32(smem);

    const int tid = threadIdx.x;
    const int lid = tid & 31;
    const int wm  = tid >> 5;            // warp id 0..7 = m-group
    const int qi  = (int)(gridDim.x - 1 - blockIdx.x);   // big blocks first
    const int h   = blockIdx.y;
    const int b   = blockIdx.z;
    const int q0  = qi * 128;
    const size_t base = (size_t)(b * HH + h) * TT * DD;

    // ldmatrix lane geometry (A/V: a_r/a_cb; K-as-B: b_r/b_cb)
    const int a_r  = (lid & 7) + ((lid >> 3) & 1) * 8;
    const int a_cb = (lid >> 4) * 16;
    const int b_r  = ((lid >> 4) & 1) * 8 + (lid & 7);
    const int b_cb = ((lid >> 3) & 1) * 16;

    // fill indices: 64 rows, 4 threads/row, 16 floats each
    const int f_r = tid >> 2;            // 0..63
    const int f_c = (tid & 3) * 16;      // float col base

    // ---- Stage Q (128 x 64) through smem, pre-scaled, split hi/lo ----
    {
        const float qs = 0.125f * 1.44269504f;   // 1/sqrt(D) * log2(e)
        const float* gq = g_q + base + (size_t)q0 * DD;
        #pragma unroll
        for (int half = 0; half < 2; ++half) {
            int r = f_r + half * 64;
            #pragma unroll
            for (int i = 0; i < 4; ++i) {
                float4 v = *(const float4*)(gq + (size_t)r * DD + f_c + i * 4);
                v.x *= qs; v.y *= qs; v.z *= qs; v.w *= qs;
                uint32_t h01, l01, h23, l23;
                split2(v.x, v.y, h01, l01);
                split2(v.z, v.w, h23, l23);
                int off = r * APITCH + (f_c + i * 4) * 2;
                *(uint2*)(smem + AT_KH + off) = make_uint2(h01, h23);   // Qh
                *(uint2*)(smem + AT_VH + off) = make_uint2(l01, l23);   // Ql
            }
        }
    }
    __syncthreads();

    // ---- Load Q fragments into registers (4 k-steps x 4 regs, hi+lo) ----
    uint32_t qh[4][4], ql[4][4];
    #pragma unroll
    for (int ks = 0; ks < 4; ++ks) {
        uint32_t ra = (wm * 16 + a_r) * APITCH + a_cb + ks * 32;
        ldsm_x4(qh[ks][0], qh[ks][1], qh[ks][2], qh[ks][3], sb + AT_KH + ra);
        ldsm_x4(ql[ks][0], ql[ks][1], ql[ks][2], ql[ks][3], sb + AT_VH + ra);
    }
    __syncthreads();

    float o[8][4];
    #pragma unroll
    for (int i = 0; i < 8; i++)
        #pragma unroll
        for (int j = 0; j < 4; j++) o[i][j] = 0.f;
    float m0 = -1e30f, m1 = -1e30f, l0 = 0.f, l1 = 0.f;

    const int row_min = q0 + wm * 16;
    const int r0g = row_min + (lid >> 2);     // global q row (first half)
    const int col_e = (lid & 3) * 2;

    const int ntiles = 2 * qi + 2;
    for (int j = 0; j < ntiles; ++j) {
        // ---- fill K/V tiles (64x64), split hi/lo bf16 ----
        {
            const float* gk = g_k + base + (size_t)j * 64 * DD;
            const float* gv = g_v + base + (size_t)j * 64 * DD;
            #pragma unroll
            for (int i = 0; i < 4; ++i) {
                float4 kv4 = *(const float4*)(gk + (size_t)f_r * DD + f_c + i * 4);
                float4 vv4 = *(const float4*)(gv + (size_t)f_r * DD + f_c + i * 4);
                uint32_t h01, l01, h23, l23;
                int off = f_r * APITCH + (f_c + i * 4) * 2;
                split2(kv4.x, kv4.y, h01, l01);
                split2(kv4.z, kv4.w, h23, l23);
                *(uint2*)(smem + AT_KH + off) = make_uint2(h01, h23);
                *(uint2*)(smem + AT_KL + off) = make_uint2(l01, l23);
                split2(vv4.x, vv4.y, h01, l01);
                split2(vv4.z, vv4.w, h23, l23);
                *(uint2*)(smem + AT_VH + off) = make_uint2(h01, h23);
                *(uint2*)(smem + AT_VL + off) = make_uint2(l01, l23);
            }
        }
        __syncthreads();

        // ---- S = Q K^T (3-term split) ----
        float s[8][4];
        #pragma unroll
        for (int i = 0; i < 8; i++)
            #pragma unroll
            for (int q = 0; q < 4; q++) s[i][q] = 0.f;

        #pragma unroll
        for (int ks = 0; ks < 4; ++ks) {
            uint32_t bh[4][4], bl[4][4];
            #pragma unroll
            for (int ng = 0; ng < 4; ++ng) {
                uint32_t rb = (ng * 16 + b_r) * APITCH + b_cb + ks * 32;
                ldsm_x4(bh[ng][0], bh[ng][1], bh[ng][2], bh[ng][3], sb + AT_KH + rb);
                ldsm_x4(bl[ng][0], bl[ng][1], bl[ng][2], bl[ng][3], sb + AT_KL + rb);
            }
            #pragma unroll
            for (int nt = 0; nt < 8; ++nt) {
                uint32_t b0h = bh[nt >> 1][(nt & 1) * 2];
                uint32_t b1h = bh[nt >> 1][(nt & 1) * 2 + 1];
                uint32_t b0l = bl[nt >> 1][(nt & 1) * 2];
                uint32_t b1l = bl[nt >> 1][(nt & 1) * 2 + 1];
                mma_bf16(s[nt], qh[ks][0], qh[ks][1], qh[ks][2], qh[ks][3], b0h, b1h);
                mma_bf16(s[nt], qh[ks][0], qh[ks][1], qh[ks][2], qh[ks][3], b0l, b1l);
                mma_bf16(s[nt], ql[ks][0], ql[ks][1], ql[ks][2], ql[ks][3], b0h, b1h);
            }
        }

        // ---- causal mask (only tiles crossing this warp's diagonal) ----
        if (j * 64 + 63 > row_min) {
            #pragma unroll
            for (int nt = 0; nt < 8; ++nt) {
                int c0 = j * 64 + nt * 8 + col_e;
                if (c0     > r0g)     s[nt][0] = -1e30f;
                if (c0 + 1 > r0g)     s[nt][1] = -1e30f;
                if (c0     > r0g + 8) s[nt][2] = -1e30f;
                if (c0 + 1 > r0g + 8) s[nt][3] = -1e30f;
            }
        }

        // ---- online softmax (base-2, in fragments) ----
        float mx0 = -1e30f, mx1 = -1e30f;
        #pragma unroll
        for (int nt = 0; nt < 8; ++nt) {
            mx0 = fmaxf(mx0, fmaxf(s[nt][0], s[nt][1]));
            mx1 = fmaxf(mx1, fmaxf(s[nt][2], s[nt][3]));
        }
        mx0 = fmaxf(mx0, __shfl_xor_sync(0xffffffffu, mx0, 1));
        mx0 = fmaxf(mx0, __shfl_xor_sync(0xffffffffu, mx0, 2));
        mx1 = fmaxf(mx1, __shfl_xor_sync(0xffffffffu, mx1, 1));
        mx1 = fmaxf(mx1, __shfl_xor_sync(0xffffffffu, mx1, 2));
        float m0n = fmaxf(m0, mx0), m1n = fmaxf(m1, mx1);
        float f0 = exp2f(m0 - m0n), f1 = exp2f(m1 - m1n);
        m0 = m0n; m1 = m1n;

        float sum0 = 0.f, sum1 = 0.f;
        #pragma unroll
        for (int nt = 0; nt < 8; ++nt) {
            s[nt][0] = exp2f(s[nt][0] - m0n);
            s[nt][1] = exp2f(s[nt][1] - m0n);
            s[nt][2] = exp2f(s[nt][2] - m1n);
            s[nt][3] = exp2f(s[nt][3] - m1n);
            sum0 += s[nt][0] + s[nt][1];
            sum1 += s[nt][2] + s[nt][3];
        }
        sum0 += __shfl_xor_sync(0xffffffffu, sum0, 1);
        sum0 += __shfl_xor_sync(0xffffffffu, sum0, 2);
        sum1 += __shfl_xor_sync(0xffffffffu, sum1, 1);
        sum1 += __shfl_xor_sync(0xffffffffu, sum1, 2);
        l0 = l0 * f0 + sum0;
        l1 = l1 * f1 + sum1;

        #pragma unroll
        for (int nt = 0; nt < 8; ++nt) {
            o[nt][0] *= f0; o[nt][1] *= f0;
            o[nt][2] *= f1; o[nt][3] *= f1;
        }

        // ---- O += P V (3-term split; P fragments built in registers) ----
        #pragma unroll
        for (int ks = 0; ks < 4; ++ks) {
            uint32_t pah[4], pal[4];
            packP(s[2*ks    ][0], s[2*ks    ][1], pah[0], pal[0]);
            packP(s[2*ks    ][2], s[2*ks    ][3], pah[1], pal[1]);
            packP(s[2*ks + 1][0], s[2*ks + 1][1], pah[2], pal[2]);
            packP(s[2*ks + 1][2], s[2*ks + 1][3], pah[3], pal[3]);
            #pragma unroll
            for (int dg = 0; dg < 4; ++dg) {
                uint32_t vh[4], vl[4];
                uint32_t rv = (ks * 16 + a_r) * APITCH + dg * 32 + a_cb;
                ldsm_x4_t(vh[0], vh[1], vh[2], vh[3], sb + AT_VH + rv);
                ldsm_x4_t(vl[0], vl[1], vl[2], vl[3], sb + AT_VL + rv);
                int nt = dg * 2;
                mma_bf16(o[nt],     pah[0], pah[1], pah[2], pah[3], vh[0], vh[1]);
                mma_bf16(o[nt],     pah[0], pah[1], pah[2], pah[3], vl[0], vl[1]);
                mma_bf16(o[nt],     pal[0], pal[1], pal[2], pal[3], vh[0], vh[1]);
                mma_bf16(o[nt + 1], pah[0], pah[1], pah[2], pah[3], vh[2], vh[3]);
                mma_bf16(o[nt + 1], pah[0], pah[1], pah[2], pah[3], vl[2], vl[3]);
                mma_bf16(o[nt + 1], pal[0], pal[1], pal[2], pal[3], vh[2], vh[3]);
            }
        }
        __syncthreads();
    }

    // ---- finalize: divide by l, write [B,T,C] ----
    {
        float inv0 = 1.0f / l0, inv1 = 1.0f / l1;
        #pragma unroll
        for (int nt = 0; nt < 8; ++nt) {
            int c = h * 64 + nt * 8 + col_e;
            float2 v0 = make_float2(o[nt][0] * inv0, o[nt][1] * inv0);
            float2 v1 = make_float2(o[nt][2] * inv1, o[nt][3] * inv1);
            *(float2*)(out + (size_t)(b * TT + r0g)     * CC + c) = v0;
            *(float2*)(out + (size_t)(b * TT + r0g + 8) * CC + c) = v1;
        }
    }
}

// ---------------------------------------------------------------------------
extern "C" void kernel_launch(void* const* d_in, const int* in_sizes, int n_in,
                              void* d_out, int out_size)
{
    const float* x    = (const float*)d_in[0];   // [2,2048,1024]
    const float* w    = (const float*)d_in[1];   // [1024,3072]
    const float* bias = (const float*)d_in[2];   // [3072]
    float* out = (float*)d_out;                  // [2,2048,1024]

    cudaFuncSetAttribute((const void*)qkv_gemm_mma,
                         cudaFuncAttributeMaxDynamicSharedMemorySize, GEMM_SMEM);
    cudaFuncSetAttribute((const void*)attn_mma,
                         cudaFuncAttributeMaxDynamicSharedMemorySize, ATTN_SMEM);

    qkv_gemm_mma<<<dim3(N3 / 128, MM / 128), 256, GEMM_SMEM>>>(x, w, bias);
    attn_mma<<<dim3(TT / 128, HH, BB), 256, ATTN_SMEM>>>(out);
}

// round 5
// speedup vs baseline: 2.8049x; 1.1177x over previous
#include <cuda_runtime.h>
#include <cuda_bf16.h>
#include <cstdint>
#include <math.h>

// Problem constants
#define BB  2
#define TT  2048
#define CC  1024
#define HH  16
#define DD  64
#define N3  (3*CC)      // 3072
#define MM  (BB*TT)     // 4096

// Scratch for Q,K,V in [B,H,T,D] layout (device globals: allocation-free)
__device__ float g_q[BB*HH*TT*DD];
__device__ float g_k[BB*HH*TT*DD];
__device__ float g_v[BB*HH*TT*DD];

// ===========================================================================
// Portable PTX helpers (sm_80+; legal on plain compute_103 target)
// ===========================================================================
__device__ __forceinline__ uint32_t smem_u32(const void* p) {
    uint32_t a;
    asm("{ .reg .u64 t; cvta.to.shared.u64 t, %1; cvt.u32.u64 %0, t; }"
        : "=r"(a) : "l"(p));
    return a;
}

__device__ __forceinline__ void ldsm_x4(uint32_t& r0, uint32_t& r1,
                                        uint32_t& r2, uint32_t& r3,
                                        uint32_t addr) {
    asm volatile("ldmatrix.sync.aligned.m8n8.x4.shared.b16 {%0,%1,%2,%3}, [%4];"
                 : "=r"(r0), "=r"(r1), "=r"(r2), "=r"(r3) : "r"(addr));
}

__device__ __forceinline__ void ldsm_x4_t(uint32_t& r0, uint32_t& r1,
                                          uint32_t& r2, uint32_t& r3,
                                          uint32_t addr) {
    asm volatile("ldmatrix.sync.aligned.m8n8.x4.trans.shared.b16 {%0,%1,%2,%3}, [%4];"
                 : "=r"(r0), "=r"(r1), "=r"(r2), "=r"(r3) : "r"(addr));
}

__device__ __forceinline__ void mma_bf16(float* c,
                                         uint32_t a0, uint32_t a1,
                                         uint32_t a2, uint32_t a3,
                                         uint32_t b0, uint32_t b1) {
    asm volatile(
        "mma.sync.aligned.m16n8k16.row.col.f32.bf16.bf16.f32 "
        "{%0,%1,%2,%3}, {%4,%5,%6,%7}, {%8,%9}, {%0,%1,%2,%3};"
        : "+f"(c[0]), "+f"(c[1]), "+f"(c[2]), "+f"(c[3])
        : "r"(a0), "r"(a1), "r"(a2), "r"(a3), "r"(b0), "r"(b1));
}

// split fp32 -> (hi-bf16 pair [trunc], lo-bf16 pair [residual]) for 2 values
__device__ __forceinline__ void split2(float v0, float v1,
                                       uint32_t& h, uint32_t& l) {
    uint32_t u0 = __float_as_uint(v0), u1 = __float_as_uint(v1);
    h = __byte_perm(u0, u1, 0x7632);               // hi16(v1):hi16(v0)
    float l0 = v0 - __uint_as_float(u0 & 0xFFFF0000u);
    float l1 = v1 - __uint_as_float(u1 & 0xFFFF0000u);
    asm("cvt.rn.bf16x2.f32 %0, %1, %2;" : "=r"(l) : "f"(l1), "f"(l0));
}

// split softmax prob pair -> rn-bf16 pack + residual pack
__device__ __forceinline__ void packP(float p0, float p1,
                                      uint32_t& hi, uint32_t& lo) {
    asm("cvt.rn.bf16x2.f32 %0, %1, %2;" : "=r"(hi) : "f"(p1), "f"(p0));
    float h0 = __uint_as_float(hi << 16);
    float h1 = __uint_as_float(hi & 0xFFFF0000u);
    float r0 = p0 - h0, r1 = p1 - h1;
    asm("cvt.rn.bf16x2.f32 %0, %1, %2;" : "=r"(lo) : "f"(r1), "f"(r0));
}

// ===========================================================================
// Kernel 1: QKV = x @ w + b via mma.sync bf16x3 (split precision)
// CTA tile M=128 N=128, BK=32, 256 threads. Single-sync software pipeline:
// prefetch regs(it+1) -> compute(it) -> store(it+1) -> sync.
// B^T loaded directly with coalesced 32-bit strided loads (no fp32 stage).
// ===========================================================================
#define TILE_BYTES 10240            // 128 rows * 80B
#define PITCH      80
#define GEMM_SMEM  (8 * TILE_BYTES) // 81920

__global__ __launch_bounds__(256, 1)
void qkv_gemm_mma(const float* __restrict__ x,
                  const float* __restrict__ w,
                  const float* __restrict__ bias)
{
    extern __shared__ char smem[];
    const uint32_t sb = smem_u32(smem);

    const int tid = threadIdx.x;
    const int lid = tid & 31;
    const int wid = tid >> 5;
    const int wm  = wid & 3;
    const int wn  = wid >> 2;
    const int n0  = blockIdx.x * 128;
    const int m0  = blockIdx.y * 128;

    // A load indices: 128 rows x 32 k, float4 per thread x4 passes
    const int a_m  = tid >> 3;              // 0..31
    const int a_k4 = tid & 7;               // float4 index along k
    // B load indices: thread = one n column, one 16-wide k half
    const int b_n  = tid & 127;             // 0..127
    const int b_kh = (tid >> 7) * 16;       // 0 or 16

    // ldmatrix lane geometry
    const int a_r  = (lid & 7) + ((lid >> 3) & 1) * 8;
    const int a_cb = (lid >> 4) * 16;
    const int b_r  = ((lid >> 4) & 1) * 8 + (lid & 7);
    const int b_cb = ((lid >> 3) & 1) * 16;

    float acc[2][8][4];
    #pragma unroll
    for (int i = 0; i < 2; i++)
        #pragma unroll
        for (int j = 0; j < 8; j++)
            #pragma unroll
            for (int q = 0; q < 4; q++) acc[i][j][q] = 0.f;

    const float* xp = x + (size_t)m0 * CC;
    const float* wp = w + n0 + b_n;

    float4 ax[4];
    float  bxr[16];

    auto load_regs = [&](int k0) {
        #pragma unroll
        for (int p = 0; p < 4; ++p) {
            int m = a_m + p * 32;
            ax[p] = *(const float4*)(xp + (size_t)m * CC + k0 + a_k4 * 4);
        }
        const float* wb = wp + (size_t)(k0 + b_kh) * N3;
        #pragma unroll
        for (int q = 0; q < 16; ++q)
            bxr[q] = wb[(size_t)q * N3];
    };
    auto store_tiles = [&](int buf) {
        char* Ah = smem + (buf * 4 + 0) * TILE_BYTES;
        char* Al = smem + (buf * 4 + 1) * TILE_BYTES;
        char* Bh = smem + (buf * 4 + 2) * TILE_BYTES;
        char* Bl = smem + (buf * 4 + 3) * TILE_BYTES;
        #pragma unroll
        for (int p = 0; p < 4; ++p) {
            int m = a_m + p * 32;
            uint32_t h01, l01, h23, l23;
            split2(ax[p].x, ax[p].y, h01, l01);
            split2(ax[p].z, ax[p].w, h23, l23);
            int off = m * PITCH + a_k4 * 8;
            *(uint2*)(Ah + off) = make_uint2(h01, h23);
            *(uint2*)(Al + off) = make_uint2(l01, l23);
        }
        #pragma unroll
        for (int q = 0; q < 4; ++q) {
            uint32_t h01, l01, h23, l23;
            split2(bxr[q * 4 + 0], bxr[q * 4 + 1], h01, l01);
            split2(bxr[q * 4 + 2], bxr[q * 4 + 3], h23, l23);
            int off = b_n * PITCH + (b_kh + q * 4) * 2;
            *(uint2*)(Bh + off) = make_uint2(h01, h23);
            *(uint2*)(Bl + off) = make_uint2(l01, l23);
        }
    };
    auto compute = [&](int buf) {
        const uint32_t Ah = sb + (buf * 4 + 0) * TILE_BYTES;
        const uint32_t Al = sb + (buf * 4 + 1) * TILE_BYTES;
        const uint32_t Bh = sb + (buf * 4 + 2) * TILE_BYTES;
        const uint32_t Bl = sb + (buf * 4 + 3) * TILE_BYTES;
        #pragma unroll
        for (int ks = 0; ks < 2; ++ks) {
            const int kb = ks * 32;
            uint32_t ah[2][4], al[2][4], bh[4][4], bl[4][4];
            #pragma unroll
            for (int mt = 0; mt < 2; ++mt) {
                uint32_t ra = (wm * 32 + mt * 16 + a_r) * PITCH + a_cb + kb;
                ldsm_x4(ah[mt][0], ah[mt][1], ah[mt][2], ah[mt][3], Ah + ra);
                ldsm_x4(al[mt][0], al[mt][1], al[mt][2], al[mt][3], Al + ra);
            }
            #pragma unroll
            for (int bt = 0; bt < 4; ++bt) {
                uint32_t rb = (wn * 64 + bt * 16 + b_r) * PITCH + b_cb + kb;
                ldsm_x4(bh[bt][0], bh[bt][1], bh[bt][2], bh[bt][3], Bh + rb);
                ldsm_x4(bl[bt][0], bl[bt][1], bl[bt][2], bl[bt][3], Bl + rb);
            }
            #pragma unroll
            for (int mt = 0; mt < 2; ++mt)
                #pragma unroll
                for (int nt = 0; nt < 8; ++nt) {
                    uint32_t b0h = bh[nt >> 1][(nt & 1) * 2];
                    uint32_t b1h = bh[nt >> 1][(nt & 1) * 2 + 1];
                    uint32_t b0l = bl[nt >> 1][(nt & 1) * 2];
                    uint32_t b1l = bl[nt >> 1][(nt & 1) * 2 + 1];
                    mma_bf16(acc[mt][nt], ah[mt][0], ah[mt][1], ah[mt][2], ah[mt][3], b0h, b1h);
                    mma_bf16(acc[mt][nt], ah[mt][0], ah[mt][1], ah[mt][2], ah[mt][3], b0l, b1l);
                    mma_bf16(acc[mt][nt], al[mt][0], al[mt][1], al[mt][2], al[mt][3], b0h, b1h);
                }
        }
    };

    // ---- pipeline: 1 sync per iteration ----
    load_regs(0);
    store_tiles(0);
    __syncthreads();

    for (int it = 0; it < 32; ++it) {
        if (it < 31) load_regs((it + 1) * 32);
        compute(it & 1);
        if (it < 31) store_tiles((it + 1) & 1);
        __syncthreads();
    }

    // ---- epilogue: +bias, scatter to g_q/g_k/g_v [B,H,T,D] ----
    {
        const int n_warp = n0 + wn * 64;
        const int which  = n_warp >> 10;
        const int ccn    = n_warp & (CC - 1);
        const int h      = ccn >> 6;
        float* dst = (which == 0) ? g_q : ((which == 1) ? g_k : g_v);

        #pragma unroll
        for (int mt = 0; mt < 2; ++mt) {
            int gm = m0 + wm * 32 + mt * 16 + (lid >> 2);
            #pragma unroll
            for (int half = 0; half < 2; ++half) {
                int gmr = gm + half * 8;
                int bb = gmr >> 11;
                int t  = gmr & (TT - 1);
                float* drow = dst + ((size_t)(bb * HH + h) * TT + t) * DD;
                #pragma unroll
                for (int nt = 0; nt < 8; ++nt) {
                    int d = nt * 8 + (lid & 3) * 2;
                    float2 bv = *(const float2*)(bias + n_warp + d);
                    float2 o;
                    o.x = acc[mt][nt][half * 2 + 0] + bv.x;
                    o.y = acc[mt][nt][half * 2 + 1] + bv.y;
                    *(float2*)(drow + d) = o;
                }
            }
        }
    }
}

// ===========================================================================
// Kernel 2: causal flash attention via mma.sync bf16 split precision.
// CTA: 128 q-rows (8 warps x 16), KV tiles of 64. Softmax in registers.
// Double-buffered K/V tiles, register prefetch, 1 sync per tile.
// ===========================================================================
#define APITCH    144
#define ABUF      36864              // one buffer: KH,KL,VH,VL @ 9216 each
#define AT_KH     0
#define AT_KL     9216
#define AT_VH     18432
#define AT_VL     27648
#define ATTN_SMEM (2 * ABUF)         // 73728

__global__ __launch_bounds__(256, 1)
void attn_mma(float* __restrict__ out)
{
    extern __shared__ char smem[];
    const uint32_t sb = smem_u32(smem);

    const int tid = threadIdx.x;
    const int lid = tid & 31;
    const int wm  = tid >> 5;            // warp id 0..7 = m-group
    const int qi  = (int)(gridDim.x - 1 - blockIdx.x);   // big blocks first
    const int h   = blockIdx.y;
    const int b   = blockIdx.z;
    const int q0  = qi * 128;
    const size_t base = (size_t)(b * HH + h) * TT * DD;

    // ldmatrix lane geometry (A/V: a_r/a_cb; K-as-B: b_r/b_cb)
    const int a_r  = (lid & 7) + ((lid >> 3) & 1) * 8;
    const int a_cb = (lid >> 4) * 16;
    const int b_r  = ((lid >> 4) & 1) * 8 + (lid & 7);
    const int b_cb = ((lid >> 3) & 1) * 16;

    // fill indices: 64 rows, 4 threads/row, 16 floats each
    const int f_r = tid >> 2;            // 0..63
    const int f_c = (tid & 3) * 16;      // float col base

    // ---- Stage Q (128 x 64) through buf0 smem, pre-scaled, split hi/lo ----
    {
        const float qs = 0.125f * 1.44269504f;   // 1/sqrt(D) * log2(e)
        const float* gq = g_q + base + (size_t)q0 * DD;
        #pragma unroll
        for (int half = 0; half < 2; ++half) {
            int r = f_r + half * 64;
            #pragma unroll
            for (int i = 0; i < 4; ++i) {
                float4 v = *(const float4*)(gq + (size_t)r * DD + f_c + i * 4);
                v.x *= qs; v.y *= qs; v.z *= qs; v.w *= qs;
                uint32_t h01, l01, h23, l23;
                split2(v.x, v.y, h01, l01);
                split2(v.z, v.w, h23, l23);
                int off = r * APITCH + (f_c + i * 4) * 2;
                *(uint2*)(smem + 0     + off) = make_uint2(h01, h23);   // Qh
                *(uint2*)(smem + 18432 + off) = make_uint2(l01, l23);   // Ql
            }
        }
    }
    __syncthreads();

    // ---- Load Q fragments into registers (4 k-steps x 4 regs, hi+lo) ----
    uint32_t qh[4][4], ql[4][4];
    #pragma unroll
    for (int ks = 0; ks < 4; ++ks) {
        uint32_t ra = (wm * 16 + a_r) * APITCH + a_cb + ks * 32;
        ldsm_x4(qh[ks][0], qh[ks][1], qh[ks][2], qh[ks][3], sb + 0 + ra);
        ldsm_x4(ql[ks][0], ql[ks][1], ql[ks][2], ql[ks][3], sb + 18432 + ra);
    }
    __syncthreads();

    float o[8][4];
    #pragma unroll
    for (int i = 0; i < 8; i++)
        #pragma unroll
        for (int j = 0; j < 4; j++) o[i][j] = 0.f;
    float m0 = -1e30f, m1 = -1e30f, l0 = 0.f, l1 = 0.f;

    const int row_min = q0 + wm * 16;
    const int r0g = row_min + (lid >> 2);     // global q row (first half)
    const int col_e = (lid & 3) * 2;

    float4 kreg[4], vreg[4];
    auto load_kv_regs = [&](int j) {
        const float* gk = g_k + base + (size_t)j * 64 * DD + (size_t)f_r * DD + f_c;
        const float* gv = g_v + base + (size_t)j * 64 * DD + (size_t)f_r * DD + f_c;
        #pragma unroll
        for (int i = 0; i < 4; ++i) {
            kreg[i] = *(const float4*)(gk + i * 4);
            vreg[i] = *(const float4*)(gv + i * 4);
        }
    };
    auto store_kv = [&](int buf) {
        char* bp = smem + buf * ABUF;
        #pragma unroll
        for (int i = 0; i < 4; ++i) {
            uint32_t h01, l01, h23, l23;
            int off = f_r * APITCH + (f_c + i * 4) * 2;
            split2(kreg[i].x, kreg[i].y, h01, l01);
            split2(kreg[i].z, kreg[i].w, h23, l23);
            *(uint2*)(bp + AT_KH + off) = make_uint2(h01, h23);
            *(uint2*)(bp + AT_KL + off) = make_uint2(l01, l23);
            split2(vreg[i].x, vreg[i].y, h01, l01);
            split2(vreg[i].z, vreg[i].w, h23, l23);
            *(uint2*)(bp + AT_VH + off) = make_uint2(h01, h23);
            *(uint2*)(bp + AT_VL + off) = make_uint2(l01, l23);
        }
    };

    const int ntiles = 2 * qi + 2;
    load_kv_regs(0);
    store_kv(0);
    __syncthreads();

    for (int j = 0; j < ntiles; ++j) {
        const uint32_t bufb = sb + (j & 1) * ABUF;

        if (j + 1 < ntiles) load_kv_regs(j + 1);

        // ---- S = Q K^T (3-term split) ----
        float s[8][4];
        #pragma unroll
        for (int i = 0; i < 8; i++)
            #pragma unroll
            for (int q = 0; q < 4; q++) s[i][q] = 0.f;

        #pragma unroll
        for (int ks = 0; ks < 4; ++ks) {
            uint32_t bh[4][4], bl[4][4];
            #pragma unroll
            for (int ng = 0; ng < 4; ++ng) {
                uint32_t rb = (ng * 16 + b_r) * APITCH + b_cb + ks * 32;
                ldsm_x4(bh[ng][0], bh[ng][1], bh[ng][2], bh[ng][3], bufb + AT_KH + rb);
                ldsm_x4(bl[ng][0], bl[ng][1], bl[ng][2], bl[ng][3], bufb + AT_KL + rb);
            }
            #pragma unroll
            for (int nt = 0; nt < 8; ++nt) {
                uint32_t b0h = bh[nt >> 1][(nt & 1) * 2];
                uint32_t b1h = bh[nt >> 1][(nt & 1) * 2 + 1];
                uint32_t b0l = bl[nt >> 1][(nt & 1) * 2];
                uint32_t b1l = bl[nt >> 1][(nt & 1) * 2 + 1];
                mma_bf16(s[nt], qh[ks][0], qh[ks][1], qh[ks][2], qh[ks][3], b0h, b1h);
                mma_bf16(s[nt], qh[ks][0], qh[ks][1], qh[ks][2], qh[ks][3], b0l, b1l);
                mma_bf16(s[nt], ql[ks][0], ql[ks][1], ql[ks][2], ql[ks][3], b0h, b1h);
            }
        }

        // ---- causal mask (only tiles crossing this warp's diagonal) ----
        if (j * 64 + 63 > row_min) {
            #pragma unroll
            for (int nt = 0; nt < 8; ++nt) {
                int c0 = j * 64 + nt * 8 + col_e;
                if (c0     > r0g)     s[nt][0] = -1e30f;
                if (c0 + 1 > r0g)     s[nt][1] = -1e30f;
                if (c0     > r0g + 8) s[nt][2] = -1e30f;
                if (c0 + 1 > r0g + 8) s[nt][3] = -1e30f;
            }
        }

        // ---- online softmax (base-2, in fragments) ----
        float mx0 = -1e30f, mx1 = -1e30f;
        #pragma unroll
        for (int nt = 0; nt < 8; ++nt) {
            mx0 = fmaxf(mx0, fmaxf(s[nt][0], s[nt][1]));
            mx1 = fmaxf(mx1, fmaxf(s[nt][2], s[nt][3]));
        }
        mx0 = fmaxf(mx0, __shfl_xor_sync(0xffffffffu, mx0, 1));
        mx0 = fmaxf(mx0, __shfl_xor_sync(0xffffffffu, mx0, 2));
        mx1 = fmaxf(mx1, __shfl_xor_sync(0xffffffffu, mx1, 1));
        mx1 = fmaxf(mx1, __shfl_xor_sync(0xffffffffu, mx1, 2));
        float m0n = fmaxf(m0, mx0), m1n = fmaxf(m1, mx1);
        float f0 = exp2f(m0 - m0n), f1 = exp2f(m1 - m1n);
        m0 = m0n; m1 = m1n;

        float sum0 = 0.f, sum1 = 0.f;
        #pragma unroll
        for (int nt = 0; nt < 8; ++nt) {
            s[nt][0] = exp2f(s[nt][0] - m0n);
            s[nt][1] = exp2f(s[nt][1] - m0n);
            s[nt][2] = exp2f(s[nt][2] - m1n);
            s[nt][3] = exp2f(s[nt][3] - m1n);
            sum0 += s[nt][0] + s[nt][1];
            sum1 += s[nt][2] + s[nt][3];
        }
        sum0 += __shfl_xor_sync(0xffffffffu, sum0, 1);
        sum0 += __shfl_xor_sync(0xffffffffu, sum0, 2);
        sum1 += __shfl_xor_sync(0xffffffffu, sum1, 1);
        sum1 += __shfl_xor_sync(0xffffffffu, sum1, 2);
        l0 = l0 * f0 + sum0;
        l1 = l1 * f1 + sum1;

        #pragma unroll
        for (int nt = 0; nt < 8; ++nt) {
            o[nt][0] *= f0; o[nt][1] *= f0;
            o[nt][2] *= f1; o[nt][3] *= f1;
        }

        // ---- O += P V (3-term split; P fragments built in registers) ----
        #pragma unroll
        for (int ks = 0; ks < 4; ++ks) {
            uint32_t pah[4], pal[4];
            packP(s[2*ks    ][0], s[2*ks    ][1], pah[0], pal[0]);
            packP(s[2*ks    ][2], s[2*ks    ][3], pah[1], pal[1]);
            packP(s[2*ks + 1][0], s[2*ks + 1][1], pah[2], pal[2]);
            packP(s[2*ks + 1][2], s[2*ks + 1][3], pah[3], pal[3]);
            #pragma unroll
            for (int dg = 0; dg < 4; ++dg) {
                uint32_t vh[4], vl[4];
                uint32_t rv = (ks * 16 + a_r) * APITCH + dg * 32 + a_cb;
                ldsm_x4_t(vh[0], vh[1], vh[2], vh[3], bufb + AT_VH + rv);
                ldsm_x4_t(vl[0], vl[1], vl[2], vl[3], bufb + AT_VL + rv);
                int nt = dg * 2;
                mma_bf16(o[nt],     pah[0], pah[1], pah[2], pah[3], vh[0], vh[1]);
                mma_bf16(o[nt],     pah[0], pah[1], pah[2], pah[3], vl[0], vl[1]);
                mma_bf16(o[nt],     pal[0], pal[1], pal[2], pal[3], vh[0], vh[1]);
                mma_bf16(o[nt + 1], pah[0], pah[1], pah[2], pah[3], vh[2], vh[3]);
                mma_bf16(o[nt + 1], pah[0], pah[1], pah[2], pah[3], vl[2], vl[3]);
                mma_bf16(o[nt + 1], pal[0], pal[1], pal[2], pal[3], vh[2], vh[3]);
            }
        }

        if (j + 1 < ntiles) store_kv((j + 1) & 1);
        __syncthreads();
    }

    // ---- finalize: divide by l, write [B,T,C] ----
    {
        float inv0 = 1.0f / l0, inv1 = 1.0f / l1;
        #pragma unroll
        for (int nt = 0; nt < 8; ++nt) {
            int c = h * 64 + nt * 8 + col_e;
            float2 v0 = make_float2(o[nt][0] * inv0, o[nt][1] * inv0);
            float2 v1 = make_float2(o[nt][2] * inv1, o[nt][3] * inv1);
            *(float2*)(out + (size_t)(b * TT + r0g)     * CC + c) = v0;
            *(float2*)(out + (size_t)(b * TT + r0g + 8) * CC + c) = v1;
        }
    }
}

// ---------------------------------------------------------------------------
extern "C" void kernel_launch(void* const* d_in, const int* in_sizes, int n_in,
                              void* d_out, int out_size)
{
    const float* x    = (const float*)d_in[0];   // [2,2048,1024]
    const float* w    = (const float*)d_in[1];   // [1024,3072]
    const float* bias = (const float*)d_in[2];   // [3072]
    float* out = (float*)d_out;                  // [2,2048,1024]

    cudaFuncSetAttribute((const void*)qkv_gemm_mma,
                         cudaFuncAttributeMaxDynamicSharedMemorySize, GEMM_SMEM);
    cudaFuncSetAttribute((const void*)attn_mma,
                         cudaFuncAttributeMaxDynamicSharedMemorySize, ATTN_SMEM);

    qkv_gemm_mma<<<dim3(N3 / 128, MM / 128), 256, GEMM_SMEM>>>(x, w, bias);
    attn_mma<<<dim3(TT / 128, HH, BB), 256, ATTN_SMEM>>>(out);
}

// round 6
// speedup vs baseline: 3.1823x; 1.1345x over previous
#include <cuda_runtime.h>
#include <cuda_bf16.h>
#include <cuda_fp16.h>
#include <cstdint>
#include <math.h>

// Problem constants
#define BB  2
#define TT  2048
#define CC  1024
#define HH  16
#define DD  64
#define N3  (3*CC)      // 3072
#define MM  (BB*TT)     // 4096

// Scratch for Q,K,V in [B,H,T,D] layout (device globals: allocation-free)
__device__ float g_q[BB*HH*TT*DD];
__device__ float g_k[BB*HH*TT*DD];
__device__ float g_v[BB*HH*TT*DD];

// ===========================================================================
// Portable PTX helpers (sm_80+; legal on plain compute_103 target)
// ===========================================================================
__device__ __forceinline__ uint32_t smem_u32(const void* p) {
    uint32_t a;
    asm("{ .reg .u64 t; cvta.to.shared.u64 t, %1; cvt.u32.u64 %0, t; }"
        : "=r"(a) : "l"(p));
    return a;
}

__device__ __forceinline__ void ldsm_x4(uint32_t& r0, uint32_t& r1,
                                        uint32_t& r2, uint32_t& r3,
                                        uint32_t addr) {
    asm volatile("ldmatrix.sync.aligned.m8n8.x4.shared.b16 {%0,%1,%2,%3}, [%4];"
                 : "=r"(r0), "=r"(r1), "=r"(r2), "=r"(r3) : "r"(addr));
}

__device__ __forceinline__ void ldsm_x4_t(uint32_t& r0, uint32_t& r1,
                                          uint32_t& r2, uint32_t& r3,
                                          uint32_t addr) {
    asm volatile("ldmatrix.sync.aligned.m8n8.x4.trans.shared.b16 {%0,%1,%2,%3}, [%4];"
                 : "=r"(r0), "=r"(r1), "=r"(r2), "=r"(r3) : "r"(addr));
}

__device__ __forceinline__ void mma_bf16(float* c,
                                         uint32_t a0, uint32_t a1,
                                         uint32_t a2, uint32_t a3,
                                         uint32_t b0, uint32_t b1) {
    asm volatile(
        "mma.sync.aligned.m16n8k16.row.col.f32.bf16.bf16.f32 "
        "{%0,%1,%2,%3}, {%4,%5,%6,%7}, {%8,%9}, {%0,%1,%2,%3};"
        : "+f"(c[0]), "+f"(c[1]), "+f"(c[2]), "+f"(c[3])
        : "r"(a0), "r"(a1), "r"(a2), "r"(a3), "r"(b0), "r"(b1));
}

__device__ __forceinline__ void mma_f16(float* c,
                                        uint32_t a0, uint32_t a1,
                                        uint32_t a2, uint32_t a3,
                                        uint32_t b0, uint32_t b1) {
    asm volatile(
        "mma.sync.aligned.m16n8k16.row.col.f32.f16.f16.f32 "
        "{%0,%1,%2,%3}, {%4,%5,%6,%7}, {%8,%9}, {%0,%1,%2,%3};"
        : "+f"(c[0]), "+f"(c[1]), "+f"(c[2]), "+f"(c[3])
        : "r"(a0), "r"(a1), "r"(a2), "r"(a3), "r"(b0), "r"(b1));
}

// split fp32 -> (hi-bf16 pair [trunc], lo-bf16 pair [residual]) for 2 values
__device__ __forceinline__ void split2(float v0, float v1,
                                       uint32_t& h, uint32_t& l) {
    uint32_t u0 = __float_as_uint(v0), u1 = __float_as_uint(v1);
    h = __byte_perm(u0, u1, 0x7632);               // hi16(v1):hi16(v0)
    float l0 = v0 - __uint_as_float(u0 & 0xFFFF0000u);
    float l1 = v1 - __uint_as_float(u1 & 0xFFFF0000u);
    asm("cvt.rn.bf16x2.f32 %0, %1, %2;" : "=r"(l) : "f"(l1), "f"(l0));
}

// pack 2 fp32 -> rn-fp16x2 (hi only)
__device__ __forceinline__ uint32_t pack_h2(float v0, float v1) {
    uint32_t h;
    asm("cvt.rn.f16x2.f32 %0, %1, %2;" : "=r"(h) : "f"(v1), "f"(v0));
    return h;
}

// split fp32 -> (rn-fp16 pair, fp16 residual pair)
__device__ __forceinline__ void split2h(float v0, float v1,
                                        uint32_t& h, uint32_t& l) {
    asm("cvt.rn.f16x2.f32 %0, %1, %2;" : "=r"(h) : "f"(v1), "f"(v0));
    float h0, h1;
    asm("{ .reg .f16 lo, hi;\n\t"
        "  mov.b32 {lo, hi}, %2;\n\t"
        "  cvt.f32.f16 %0, lo;\n\t"
        "  cvt.f32.f16 %1, hi; }"
        : "=f"(h0), "=f"(h1) : "r"(h));
    float r0 = v0 - h0, r1 = v1 - h1;
    asm("cvt.rn.f16x2.f32 %0, %1, %2;" : "=r"(l) : "f"(r1), "f"(r0));
}

// split softmax prob pair -> rn-bf16 pack + residual pack
__device__ __forceinline__ void packP(float p0, float p1,
                                      uint32_t& hi, uint32_t& lo) {
    asm("cvt.rn.bf16x2.f32 %0, %1, %2;" : "=r"(hi) : "f"(p1), "f"(p0));
    float h0 = __uint_as_float(hi << 16);
    float h1 = __uint_as_float(hi & 0xFFFF0000u);
    float r0 = p0 - h0, r1 = p1 - h1;
    asm("cvt.rn.bf16x2.f32 %0, %1, %2;" : "=r"(lo) : "f"(r1), "f"(r0));
}

// ===========================================================================
// Kernel 1: QKV = x @ w + b via mma.sync fp16 2-term split:
//   D = Ah*Bh + Ah*Bl,  Ah = rn-fp16(x), Bh = rn-fp16(w), Bl = fp16(w - Bh)
// CTA tile M=128 N=128, BK=32, 256 threads. Single-sync software pipeline.
// ===========================================================================
#define TILE_BYTES 10240            // 128 rows * 80B
#define PITCH      80
#define GEMM_SMEM  (6 * TILE_BYTES) // 61440 (Ah,Bh,Bl x2 buffers)

__global__ __launch_bounds__(256, 1)
void qkv_gemm_mma(const float* __restrict__ x,
                  const float* __restrict__ w,
                  const float* __restrict__ bias)
{
    extern __shared__ char smem[];
    const uint32_t sb = smem_u32(smem);

    const int tid = threadIdx.x;
    const int lid = tid & 31;
    const int wid = tid >> 5;
    const int wm  = wid & 3;
    const int wn  = wid >> 2;
    const int n0  = blockIdx.x * 128;
    const int m0  = blockIdx.y * 128;

    // A load indices: 128 rows x 32 k, float4 per thread x4 passes
    const int a_m  = tid >> 3;              // 0..31
    const int a_k4 = tid & 7;               // float4 index along k
    // B load indices: thread = one n column, one 16-wide k half
    const int b_n  = tid & 127;             // 0..127
    const int b_kh = (tid >> 7) * 16;       // 0 or 16

    // ldmatrix lane geometry
    const int a_r  = (lid & 7) + ((lid >> 3) & 1) * 8;
    const int a_cb = (lid >> 4) * 16;
    const int b_r  = ((lid >> 4) & 1) * 8 + (lid & 7);
    const int b_cb = ((lid >> 3) & 1) * 16;

    float acc[2][8][4];
    #pragma unroll
    for (int i = 0; i < 2; i++)
        #pragma unroll
        for (int j = 0; j < 8; j++)
            #pragma unroll
            for (int q = 0; q < 4; q++) acc[i][j][q] = 0.f;

    const float* xp = x + (size_t)m0 * CC;
    const float* wp = w + n0 + b_n;

    float4 ax[4];
    float  bxr[16];

    auto load_regs = [&](int k0) {
        #pragma unroll
        for (int p = 0; p < 4; ++p) {
            int m = a_m + p * 32;
            ax[p] = *(const float4*)(xp + (size_t)m * CC + k0 + a_k4 * 4);
        }
        const float* wb = wp + (size_t)(k0 + b_kh) * N3;
        #pragma unroll
        for (int q = 0; q < 16; ++q)
            bxr[q] = wb[(size_t)q * N3];
    };
    auto store_tiles = [&](int buf) {
        char* Ah = smem + (buf * 3 + 0) * TILE_BYTES;
        char* Bh = smem + (buf * 3 + 1) * TILE_BYTES;
        char* Bl = smem + (buf * 3 + 2) * TILE_BYTES;
        #pragma unroll
        for (int p = 0; p < 4; ++p) {
            int m = a_m + p * 32;
            uint32_t h01 = pack_h2(ax[p].x, ax[p].y);
            uint32_t h23 = pack_h2(ax[p].z, ax[p].w);
            int off = m * PITCH + a_k4 * 8;
            *(uint2*)(Ah + off) = make_uint2(h01, h23);
        }
        #pragma unroll
        for (int q = 0; q < 4; ++q) {
            uint32_t h01, l01, h23, l23;
            split2h(bxr[q * 4 + 0], bxr[q * 4 + 1], h01, l01);
            split2h(bxr[q * 4 + 2], bxr[q * 4 + 3], h23, l23);
            int off = b_n * PITCH + (b_kh + q * 4) * 2;
            *(uint2*)(Bh + off) = make_uint2(h01, h23);
            *(uint2*)(Bl + off) = make_uint2(l01, l23);
        }
    };
    auto compute = [&](int buf) {
        const uint32_t Ah = sb + (buf * 3 + 0) * TILE_BYTES;
        const uint32_t Bh = sb + (buf * 3 + 1) * TILE_BYTES;
        const uint32_t Bl = sb + (buf * 3 + 2) * TILE_BYTES;
        #pragma unroll
        for (int ks = 0; ks < 2; ++ks) {
            const int kb = ks * 32;
            uint32_t ah[2][4], bh[4][4], bl[4][4];
            #pragma unroll
            for (int mt = 0; mt < 2; ++mt) {
                uint32_t ra = (wm * 32 + mt * 16 + a_r) * PITCH + a_cb + kb;
                ldsm_x4(ah[mt][0], ah[mt][1], ah[mt][2], ah[mt][3], Ah + ra);
            }
            #pragma unroll
            for (int bt = 0; bt < 4; ++bt) {
                uint32_t rb = (wn * 64 + bt * 16 + b_r) * PITCH + b_cb + kb;
                ldsm_x4(bh[bt][0], bh[bt][1], bh[bt][2], bh[bt][3], Bh + rb);
                ldsm_x4(bl[bt][0], bl[bt][1], bl[bt][2], bl[bt][3], Bl + rb);
            }
            #pragma unroll
            for (int mt = 0; mt < 2; ++mt)
                #pragma unroll
                for (int nt = 0; nt < 8; ++nt) {
                    uint32_t b0h = bh[nt >> 1][(nt & 1) * 2];
                    uint32_t b1h = bh[nt >> 1][(nt & 1) * 2 + 1];
                    uint32_t b0l = bl[nt >> 1][(nt & 1) * 2];
                    uint32_t b1l = bl[nt >> 1][(nt & 1) * 2 + 1];
                    mma_f16(acc[mt][nt], ah[mt][0], ah[mt][1], ah[mt][2], ah[mt][3], b0h, b1h);
                    mma_f16(acc[mt][nt], ah[mt][0], ah[mt][1], ah[mt][2], ah[mt][3], b0l, b1l);
                }
        }
    };

    // ---- pipeline: 1 sync per iteration ----
    load_regs(0);
    store_tiles(0);
    __syncthreads();

    for (int it = 0; it < 32; ++it) {
        if (it < 31) load_regs((it + 1) * 32);
        compute(it & 1);
        if (it < 31) store_tiles((it + 1) & 1);
        __syncthreads();
    }

    // ---- epilogue: +bias, scatter to g_q/g_k/g_v [B,H,T,D] ----
    {
        const int n_warp = n0 + wn * 64;
        const int which  = n_warp >> 10;
        const int ccn    = n_warp & (CC - 1);
        const int h      = ccn >> 6;
        float* dst = (which == 0) ? g_q : ((which == 1) ? g_k : g_v);

        #pragma unroll
        for (int mt = 0; mt < 2; ++mt) {
            int gm = m0 + wm * 32 + mt * 16 + (lid >> 2);
            #pragma unroll
            for (int half = 0; half < 2; ++half) {
                int gmr = gm + half * 8;
                int bb = gmr >> 11;
                int t  = gmr & (TT - 1);
                float* drow = dst + ((size_t)(bb * HH + h) * TT + t) * DD;
                #pragma unroll
                for (int nt = 0; nt < 8; ++nt) {
                    int d = nt * 8 + (lid & 3) * 2;
                    float2 bv = *(const float2*)(bias + n_warp + d);
                    float2 o;
                    o.x = acc[mt][nt][half * 2 + 0] + bv.x;
                    o.y = acc[mt][nt][half * 2 + 1] + bv.y;
                    *(float2*)(drow + d) = o;
                }
            }
        }
    }
}

// ===========================================================================
// Kernel 2: causal flash attention via mma.sync bf16 split precision.
// CTA: 128 q-rows (8 warps x 16), KV tiles of 64. Softmax in registers.
// Double-buffered K/V tiles, register prefetch, 1 sync per tile.
// ===========================================================================
#define APITCH    144
#define ABUF      36864              // one buffer: KH,KL,VH,VL @ 9216 each
#define AT_KH     0
#define AT_KL     9216
#define AT_VH     18432
#define AT_VL     27648
#define ATTN_SMEM (2 * ABUF)         // 73728

__global__ __launch_bounds__(256, 1)
void attn_mma(float* __restrict__ out)
{
    extern __shared__ char smem[];
    const uint32_t sb = smem_u32(smem);

    const int tid = threadIdx.x;
    const int lid = tid & 31;
    const int wm  = tid >> 5;            // warp id 0..7 = m-group
    const int qi  = (int)(gridDim.x - 1 - blockIdx.x);   // big blocks first
    const int h   = blockIdx.y;
    const int b   = blockIdx.z;
    const int q0  = qi * 128;
    const size_t base = (size_t)(b * HH + h) * TT * DD;

    // ldmatrix lane geometry (A/V: a_r/a_cb; K-as-B: b_r/b_cb)
    const int a_r  = (lid & 7) + ((lid >> 3) & 1) * 8;
    const int a_cb = (lid >> 4) * 16;
    const int b_r  = ((lid >> 4) & 1) * 8 + (lid & 7);
    const int b_cb = ((lid >> 3) & 1) * 16;

    // fill indices: 64 rows, 4 threads/row, 16 floats each
    const int f_r = tid >> 2;            // 0..63
    const int f_c = (tid & 3) * 16;      // float col base

    // ---- Stage Q (128 x 64) through buf0 smem, pre-scaled, split hi/lo ----
    {
        const float qs = 0.125f * 1.44269504f;   // 1/sqrt(D) * log2(e)
        const float* gq = g_q + base + (size_t)q0 * DD;
        #pragma unroll
        for (int half = 0; half < 2; ++half) {
            int r = f_r + half * 64;
            #pragma unroll
            for (int i = 0; i < 4; ++i) {
                float4 v = *(const float4*)(gq + (size_t)r * DD + f_c + i * 4);
                v.x *= qs; v.y *= qs; v.z *= qs; v.w *= qs;
                uint32_t h01, l01, h23, l23;
                split2(v.x, v.y, h01, l01);
                split2(v.z, v.w, h23, l23);
                int off = r * APITCH + (f_c + i * 4) * 2;
                *(uint2*)(smem + 0     + off) = make_uint2(h01, h23);   // Qh
                *(uint2*)(smem + 18432 + off) = make_uint2(l01, l23);   // Ql
            }
        }
    }
    __syncthreads();

    // ---- Load Q fragments into registers (4 k-steps x 4 regs, hi+lo) ----
    uint32_t qh[4][4], ql[4][4];
    #pragma unroll
    for (int ks = 0; ks < 4; ++ks) {
        uint32_t ra = (wm * 16 + a_r) * APITCH + a_cb + ks * 32;
        ldsm_x4(qh[ks][0], qh[ks][1], qh[ks][2], qh[ks][3], sb + 0 + ra);
        ldsm_x4(ql[ks][0], ql[ks][1], ql[ks][2], ql[ks][3], sb + 18432 + ra);
    }
    __syncthreads();

    float o[8][4];
    #pragma unroll
    for (int i = 0; i < 8; i++)
        #pragma unroll
        for (int j = 0; j < 4; j++) o[i][j] = 0.f;
    float m0 = -1e30f, m1 = -1e30f, l0 = 0.f, l1 = 0.f;

    const int row_min = q0 + wm * 16;
    const int r0g = row_min + (lid >> 2);     // global q row (first half)
    const int col_e = (lid & 3) * 2;

    float4 kreg[4], vreg[4];
    auto load_kv_regs = [&](int j) {
        const float* gk = g_k + base + (size_t)j * 64 * DD + (size_t)f_r * DD + f_c;
        const float* gv = g_v + base + (size_t)j * 64 * DD + (size_t)f_r * DD + f_c;
        #pragma unroll
        for (int i = 0; i < 4; ++i) {
            kreg[i] = *(const float4*)(gk + i * 4);
            vreg[i] = *(const float4*)(gv + i * 4);
        }
    };
    auto store_kv = [&](int buf) {
        char* bp = smem + buf * ABUF;
        #pragma unroll
        for (int i = 0; i < 4; ++i) {
            uint32_t h01, l01, h23, l23;
            int off = f_r * APITCH + (f_c + i * 4) * 2;
            split2(kreg[i].x, kreg[i].y, h01, l01);
            split2(kreg[i].z, kreg[i].w, h23, l23);
            *(uint2*)(bp + AT_KH + off) = make_uint2(h01, h23);
            *(uint2*)(bp + AT_KL + off) = make_uint2(l01, l23);
            split2(vreg[i].x, vreg[i].y, h01, l01);
            split2(vreg[i].z, vreg[i].w, h23, l23);
            *(uint2*)(bp + AT_VH + off) = make_uint2(h01, h23);
            *(uint2*)(bp + AT_VL + off) = make_uint2(l01, l23);
        }
    };

    const int ntiles = 2 * qi + 2;
    load_kv_regs(0);
    store_kv(0);
    __syncthreads();

    for (int j = 0; j < ntiles; ++j) {
        const uint32_t bufb = sb + (j & 1) * ABUF;

        if (j + 1 < ntiles) load_kv_regs(j + 1);

        // ---- S = Q K^T (3-term split) ----
        float s[8][4];
        #pragma unroll
        for (int i = 0; i < 8; i++)
            #pragma unroll
            for (int q = 0; q < 4; q++) s[i][q] = 0.f;

        #pragma unroll
        for (int ks = 0; ks < 4; ++ks) {
            uint32_t bh[4][4], bl[4][4];
            #pragma unroll
            for (int ng = 0; ng < 4; ++ng) {
                uint32_t rb = (ng * 16 + b_r) * APITCH + b_cb + ks * 32;
                ldsm_x4(bh[ng][0], bh[ng][1], bh[ng][2], bh[ng][3], bufb + AT_KH + rb);
                ldsm_x4(bl[ng][0], bl[ng][1], bl[ng][2], bl[ng][3], bufb + AT_KL + rb);
            }
            #pragma unroll
            for (int nt = 0; nt < 8; ++nt) {
                uint32_t b0h = bh[nt >> 1][(nt & 1) * 2];
                uint32_t b1h = bh[nt >> 1][(nt & 1) * 2 + 1];
                uint32_t b0l = bl[nt >> 1][(nt & 1) * 2];
                uint32_t b1l = bl[nt >> 1][(nt & 1) * 2 + 1];
                mma_bf16(s[nt], qh[ks][0], qh[ks][1], qh[ks][2], qh[ks][3], b0h, b1h);
                mma_bf16(s[nt], qh[ks][0], qh[ks][1], qh[ks][2], qh[ks][3], b0l, b1l);
                mma_bf16(s[nt], ql[ks][0], ql[ks][1], ql[ks][2], ql[ks][3], b0h, b1h);
            }
        }

        // ---- causal mask (only tiles crossing this warp's diagonal) ----
        if (j * 64 + 63 > row_min) {
            #pragma unroll
            for (int nt = 0; nt < 8; ++nt) {
                int c0 = j * 64 + nt * 8 + col_e;
                if (c0     > r0g)     s[nt][0] = -1e30f;
                if (c0 + 1 > r0g)     s[nt][1] = -1e30f;
                if (c0     > r0g + 8) s[nt][2] = -1e30f;
                if (c0 + 1 > r0g + 8) s[nt][3] = -1e30f;
            }
        }

        // ---- online softmax (base-2, in fragments) ----
        float mx0 = -1e30f, mx1 = -1e30f;
        #pragma unroll
        for (int nt = 0; nt < 8; ++nt) {
            mx0 = fmaxf(mx0, fmaxf(s[nt][0], s[nt][1]));
            mx1 = fmaxf(mx1, fmaxf(s[nt][2], s[nt][3]));
        }
        mx0 = fmaxf(mx0, __shfl_xor_sync(0xffffffffu, mx0, 1));
        mx0 = fmaxf(mx0, __shfl_xor_sync(0xffffffffu, mx0, 2));
        mx1 = fmaxf(mx1, __shfl_xor_sync(0xffffffffu, mx1, 1));
        mx1 = fmaxf(mx1, __shfl_xor_sync(0xffffffffu, mx1, 2));
        float m0n = fmaxf(m0, mx0), m1n = fmaxf(m1, mx1);
        float f0 = exp2f(m0 - m0n), f1 = exp2f(m1 - m1n);
        m0 = m0n; m1 = m1n;

        float sum0 = 0.f, sum1 = 0.f;
        #pragma unroll
        for (int nt = 0; nt < 8; ++nt) {
            s[nt][0] = exp2f(s[nt][0] - m0n);
            s[nt][1] = exp2f(s[nt][1] - m0n);
            s[nt][2] = exp2f(s[nt][2] - m1n);
            s[nt][3] = exp2f(s[nt][3] - m1n);
            sum0 += s[nt][0] + s[nt][1];
            sum1 += s[nt][2] + s[nt][3];
        }
        sum0 += __shfl_xor_sync(0xffffffffu, sum0, 1);
        sum0 += __shfl_xor_sync(0xffffffffu, sum0, 2);
        sum1 += __shfl_xor_sync(0xffffffffu, sum1, 1);
        sum1 += __shfl_xor_sync(0xffffffffu, sum1, 2);
        l0 = l0 * f0 + sum0;
        l1 = l1 * f1 + sum1;

        // stage next tile's smem stores here (spreads STS away from barrier)
        if (j + 1 < ntiles) store_kv((j + 1) & 1);

        #pragma unroll
        for (int nt = 0; nt < 8; ++nt) {
            o[nt][0] *= f0; o[nt][1] *= f0;
            o[nt][2] *= f1; o[nt][3] *= f1;
        }

        // ---- O += P V (3-term split; P fragments built in registers) ----
        #pragma unroll
        for (int ks = 0; ks < 4; ++ks) {
            uint32_t pah[4], pal[4];
            packP(s[2*ks    ][0], s[2*ks    ][1], pah[0], pal[0]);
            packP(s[2*ks    ][2], s[2*ks    ][3], pah[1], pal[1]);
            packP(s[2*ks + 1][0], s[2*ks + 1][1], pah[2], pal[2]);
            packP(s[2*ks + 1][2], s[2*ks + 1][3], pah[3], pal[3]);
            #pragma unroll
            for (int dg = 0; dg < 4; ++dg) {
                uint32_t vh[4], vl[4];
                uint32_t rv = (ks * 16 + a_r) * APITCH + dg * 32 + a_cb;
                ldsm_x4_t(vh[0], vh[1], vh[2], vh[3], bufb + AT_VH + rv);
                ldsm_x4_t(vl[0], vl[1], vl[2], vl[3], bufb + AT_VL + rv);
                int nt = dg * 2;
                mma_bf16(o[nt],     pah[0], pah[1], pah[2], pah[3], vh[0], vh[1]);
                mma_bf16(o[nt],     pah[0], pah[1], pah[2], pah[3], vl[0], vl[1]);
                mma_bf16(o[nt],     pal[0], pal[1], pal[2], pal[3], vh[0], vh[1]);
                mma_bf16(o[nt + 1], pah[0], pah[1], pah[2], pah[3], vh[2], vh[3]);
                mma_bf16(o[nt + 1], pah[0], pah[1], pah[2], pah[3], vl[2], vl[3]);
                mma_bf16(o[nt + 1], pal[0], pal[1], pal[2], pal[3], vh[2], vh[3]);
            }
        }

        __syncthreads();
    }

    // ---- finalize: divide by l, write [B,T,C] ----
    {
        float inv0 = 1.0f / l0, inv1 = 1.0f / l1;
        #pragma unroll
        for (int nt = 0; nt < 8; ++nt) {
            int c = h * 64 + nt * 8 + col_e;
            float2 v0 = make_float2(o[nt][0] * inv0, o[nt][1] * inv0);
            float2 v1 = make_float2(o[nt][2] * inv1, o[nt][3] * inv1);
            *(float2*)(out + (size_t)(b * TT + r0g)     * CC + c) = v0;
            *(float2*)(out + (size_t)(b * TT + r0g + 8) * CC + c) = v1;
        }
    }
}

// ---------------------------------------------------------------------------
extern "C" void kernel_launch(void* const* d_in, const int* in_sizes, int n_in,
                              void* d_out, int out_size)
{
    const float* x    = (const float*)d_in[0];   // [2,2048,1024]
    const float* w    = (const float*)d_in[1];   // [1024,3072]
    const float* bias = (const float*)d_in[2];   // [3072]
    float* out = (float*)d_out;                  // [2,2048,1024]

    cudaFuncSetAttribute((const void*)qkv_gemm_mma,
                         cudaFuncAttributeMaxDynamicSharedMemorySize, GEMM_SMEM);
    cudaFuncSetAttribute((const void*)attn_mma,
                         cudaFuncAttributeMaxDynamicSharedMemorySize, ATTN_SMEM);

    qkv_gemm_mma<<<dim3(N3 / 128, MM / 128), 256, GEMM_SMEM>>>(x, w, bias);
    attn_mma<<<dim3(TT / 128, HH, BB), 256, ATTN_SMEM>>>(out);
}

// round 7
// speedup vs baseline: 3.2854x; 1.0324x over previous
#include <cuda_runtime.h>
#include <cuda_fp16.h>
#include <cstdint>
#include <math.h>

// Problem constants
#define BB  2
#define TT  2048
#define CC  1024
#define HH  16
#define DD  64
#define N3  (3*CC)      // 3072
#define MM  (BB*TT)     // 4096

// Pre-converted operands (device globals: allocation-free)
__device__ __half g_xh[MM*CC];           // x in fp16 (hi only), [m][k]
__device__ __half g_wh[N3*CC];           // w hi, K-major [n][k]
__device__ __half g_wl[N3*CC];           // w lo residual, K-major [n][k]
// Q,K,V split fp16 pairs in [B,H,T,D]
__device__ __half g_qh[BB*HH*TT*DD];
__device__ __half g_ql[BB*HH*TT*DD];
__device__ __half g_kh[BB*HH*TT*DD];
__device__ __half g_kl[BB*HH*TT*DD];
__device__ __half g_vh[BB*HH*TT*DD];
__device__ __half g_vl[BB*HH*TT*DD];

// ===========================================================================
// Portable PTX helpers (sm_80+)
// ===========================================================================
__device__ __forceinline__ uint32_t smem_u32(const void* p) {
    uint32_t a;
    asm("{ .reg .u64 t; cvta.to.shared.u64 t, %1; cvt.u32.u64 %0, t; }"
        : "=r"(a) : "l"(p));
    return a;
}

__device__ __forceinline__ void ldsm_x4(uint32_t& r0, uint32_t& r1,
                                        uint32_t& r2, uint32_t& r3,
                                        uint32_t addr) {
    asm volatile("ldmatrix.sync.aligned.m8n8.x4.shared.b16 {%0,%1,%2,%3}, [%4];"
                 : "=r"(r0), "=r"(r1), "=r"(r2), "=r"(r3) : "r"(addr));
}

__device__ __forceinline__ void ldsm_x4_t(uint32_t& r0, uint32_t& r1,
                                          uint32_t& r2, uint32_t& r3,
                                          uint32_t addr) {
    asm volatile("ldmatrix.sync.aligned.m8n8.x4.trans.shared.b16 {%0,%1,%2,%3}, [%4];"
                 : "=r"(r0), "=r"(r1), "=r"(r2), "=r"(r3) : "r"(addr));
}

__device__ __forceinline__ void mma_f16(float* c,
                                        uint32_t a0, uint32_t a1,
                                        uint32_t a2, uint32_t a3,
                                        uint32_t b0, uint32_t b1) {
    asm volatile(
        "mma.sync.aligned.m16n8k16.row.col.f32.f16.f16.f32 "
        "{%0,%1,%2,%3}, {%4,%5,%6,%7}, {%8,%9}, {%0,%1,%2,%3};"
        : "+f"(c[0]), "+f"(c[1]), "+f"(c[2]), "+f"(c[3])
        : "r"(a0), "r"(a1), "r"(a2), "r"(a3), "r"(b0), "r"(b1));
}

// pack 2 fp32 -> rn-fp16x2
__device__ __forceinline__ uint32_t pack_h2(float v0, float v1) {
    uint32_t h;
    asm("cvt.rn.f16x2.f32 %0, %1, %2;" : "=r"(h) : "f"(v1), "f"(v0));
    return h;
}

// split fp32 -> (rn-fp16 pair, fp16 residual pair)
__device__ __forceinline__ void split2h(float v0, float v1,
                                        uint32_t& h, uint32_t& l) {
    asm("cvt.rn.f16x2.f32 %0, %1, %2;" : "=r"(h) : "f"(v1), "f"(v0));
    float h0, h1;
    asm("{ .reg .f16 a, b;\n\t"
        "  mov.b32 {a, b}, %2;\n\t"
        "  cvt.f32.f16 %0, a;\n\t"
        "  cvt.f32.f16 %1, b; }"
        : "=f"(h0), "=f"(h1) : "r"(h));
    asm("cvt.rn.f16x2.f32 %0, %1, %2;" : "=r"(l) : "f"(v1 - h1), "f"(v0 - h0));
}

#define CP16(dst, src) \
    asm volatile("cp.async.cg.shared.global [%0], [%1], 16;" \
        :: "r"(dst), "l"(src) : "memory")
#define CP_COMMIT() asm volatile("cp.async.commit_group;" ::: "memory")
#define CP_WAIT(n)  asm volatile("cp.async.wait_group %0;" :: "n"(n) : "memory")

// ===========================================================================
// Kernel 0a: x fp32 -> fp16 (hi only), same layout
// ===========================================================================
__global__ __launch_bounds__(256)
void convert_x(const float* __restrict__ x)
{
    int i = (blockIdx.x * 256 + threadIdx.x) * 4;
    float4 v = *(const float4*)(x + i);
    uint2 o = make_uint2(pack_h2(v.x, v.y), pack_h2(v.z, v.w));
    *(uint2*)((char*)g_xh + (size_t)i * 2) = o;
}

// ===========================================================================
// Kernel 0b: w [k][n] fp32 -> (wh, wl) fp16 K-major [n][k]
// ===========================================================================
__global__ __launch_bounds__(128)
void convert_w(const float* __restrict__ w)
{
    int n  = blockIdx.x * 128 + threadIdx.x;
    int k0 = blockIdx.y * 16;
    const float* wp = w + (size_t)k0 * N3 + n;
    float v[16];
    #pragma unroll
    for (int q = 0; q < 16; ++q) v[q] = wp[(size_t)q * N3];
    uint32_t hi[8], lo[8];
    #pragma unroll
    for (int q = 0; q < 8; ++q) split2h(v[2*q], v[2*q+1], hi[q], lo[q]);
    size_t off = ((size_t)n * CC + k0) * 2;
    *(uint4*)((char*)g_wh + off)      = make_uint4(hi[0], hi[1], hi[2], hi[3]);
    *(uint4*)((char*)g_wh + off + 16) = make_uint4(hi[4], hi[5], hi[6], hi[7]);
    *(uint4*)((char*)g_wl + off)      = make_uint4(lo[0], lo[1], lo[2], lo[3]);
    *(uint4*)((char*)g_wl + off + 16) = make_uint4(lo[4], lo[5], lo[6], lo[7]);
}

// ===========================================================================
// Kernel 1: QKV GEMM, fp16 2-term (Ah*Bh + Ah*Bl). cp.async, triple buffer,
// BK=64, one barrier per iteration. Epilogue: +bias, split to fp16 hi/lo QKV.
// ===========================================================================
#define GP 144
#define GT (128*GP)          // 18432
#define GEMM_SMEM (9*GT)     // 165888

__global__ __launch_bounds__(256, 1)
void qkv_gemm(const float* __restrict__ bias)
{
    extern __shared__ char smem[];
    const uint32_t sb = smem_u32(smem);

    const int tid = threadIdx.x;
    const int lid = tid & 31;
    const int wid = tid >> 5;
    const int wm  = wid & 3;
    const int wn  = wid >> 2;
    const int n0  = blockIdx.x * 128;
    const int m0  = blockIdx.y * 128;

    const int a_r  = (lid & 7) + ((lid >> 3) & 1) * 8;
    const int a_cb = (lid >> 4) * 16;
    const int b_r  = ((lid >> 4) & 1) * 8 + (lid & 7);
    const int b_cb = ((lid >> 3) & 1) * 16;

    float acc[2][8][4];
    #pragma unroll
    for (int i = 0; i < 2; i++)
        #pragma unroll
        for (int j = 0; j < 8; j++)
            #pragma unroll
            for (int q = 0; q < 4; q++) acc[i][j][q] = 0.f;

    const int c_row = tid >> 3;           // 0..31 (x4 -> 128 rows)
    const int c_c   = tid & 7;            // 16B chunk

    auto issue = [&](int it) {
        const int buf = it % 3;
        const int k0  = it * 64;
        const uint32_t s0 = sb + buf * 3 * GT;
        #pragma unroll
        for (int p = 0; p < 4; ++p) {
            int row = c_row + p * 32;
            uint32_t dst = s0 + row * GP + c_c * 16;
            const char* src = (const char*)g_xh +
                (((size_t)(m0 + row)) * CC + k0 + c_c * 8) * 2;
            CP16(dst, src);
        }
        #pragma unroll
        for (int p = 0; p < 4; ++p) {
            int row = c_row + p * 32;
            size_t go = (((size_t)(n0 + row)) * CC + k0 + c_c * 8) * 2;
            CP16(s0 + GT     + row * GP + c_c * 16, (const char*)g_wh + go);
            CP16(s0 + 2 * GT + row * GP + c_c * 16, (const char*)g_wl + go);
        }
        CP_COMMIT();
    };

    auto compute = [&](int buf) {
        const uint32_t A  = sb + buf * 3 * GT;
        const uint32_t Bh = A + GT;
        const uint32_t Bl = A + 2 * GT;
        #pragma unroll
        for (int ks = 0; ks < 4; ++ks) {
            const int kb = ks * 32;
            uint32_t ah[2][4], bh[4][4], bl[4][4];
            #pragma unroll
            for (int mt = 0; mt < 2; ++mt) {
                uint32_t ra = (wm * 32 + mt * 16 + a_r) * GP + a_cb + kb;
                ldsm_x4(ah[mt][0], ah[mt][1], ah[mt][2], ah[mt][3], A + ra);
            }
            #pragma unroll
            for (int bt = 0; bt < 4; ++bt) {
                uint32_t rb = (wn * 64 + bt * 16 + b_r) * GP + b_cb + kb;
                ldsm_x4(bh[bt][0], bh[bt][1], bh[bt][2], bh[bt][3], Bh + rb);
                ldsm_x4(bl[bt][0], bl[bt][1], bl[bt][2], bl[bt][3], Bl + rb);
            }
            #pragma unroll
            for (int mt = 0; mt < 2; ++mt)
                #pragma unroll
                for (int nt = 0; nt < 8; ++nt) {
                    uint32_t b0h = bh[nt >> 1][(nt & 1) * 2];
                    uint32_t b1h = bh[nt >> 1][(nt & 1) * 2 + 1];
                    uint32_t b0l = bl[nt >> 1][(nt & 1) * 2];
                    uint32_t b1l = bl[nt >> 1][(nt & 1) * 2 + 1];
                    mma_f16(acc[mt][nt], ah[mt][0], ah[mt][1], ah[mt][2], ah[mt][3], b0h, b1h);
                    mma_f16(acc[mt][nt], ah[mt][0], ah[mt][1], ah[mt][2], ah[mt][3], b0l, b1l);
                }
        }
    };

    issue(0);
    issue(1);
    for (int it = 0; it < 16; ++it) {
        if (it < 15) { CP_WAIT(1); } else { CP_WAIT(0); }
        __syncthreads();
        if (it + 2 < 16) issue(it + 2);
        compute(it % 3);
    }

    // Epilogue: +bias, split fp16 hi/lo, scatter to q/k/v [B,H,T,D]
    {
        const int n_warp = n0 + wn * 64;
        const int which  = n_warp >> 10;
        const int ccn    = n_warp & (CC - 1);
        const int h      = ccn >> 6;
        __half* dh = (which == 0) ? g_qh : ((which == 1) ? g_kh : g_vh);
        __half* dl = (which == 0) ? g_ql : ((which == 1) ? g_kl : g_vl);

        #pragma unroll
        for (int mt = 0; mt < 2; ++mt) {
            int gm = m0 + wm * 32 + mt * 16 + (lid >> 2);
            #pragma unroll
            for (int half = 0; half < 2; ++half) {
                int gmr = gm + half * 8;
                int bb = gmr >> 11;
                int t  = gmr & (TT - 1);
                size_t rowhw = ((size_t)(bb * HH + h) * TT + t) * DD;
                #pragma unroll
                for (int nt = 0; nt < 8; ++nt) {
                    int d = nt * 8 + (lid & 3) * 2;
                    float2 bv = *(const float2*)(bias + n_warp + d);
                    float ox = acc[mt][nt][half * 2 + 0] + bv.x;
                    float oy = acc[mt][nt][half * 2 + 1] + bv.y;
                    uint32_t hi, lo;
                    split2h(ox, oy, hi, lo);
                    *(uint32_t*)((char*)dh + (rowhw + d) * 2) = hi;
                    *(uint32_t*)((char*)dl + (rowhw + d) * 2) = lo;
                }
            }
        }
    }
}

// ===========================================================================
// Kernel 2: causal flash attention, fp16 split precision, cp.async KV tiles,
// triple buffer, one barrier per tile. Softmax in registers.
// ===========================================================================
#define AP 144
#define ATILE (64*AP)        // 9216
#define ABUF  (4*ATILE)      // 36864
#define ATTN_SMEM (3*ABUF)   // 110592

__global__ __launch_bounds__(256, 1)
void attn_mma(float* __restrict__ out)
{
    extern __shared__ char smem[];
    const uint32_t sb = smem_u32(smem);

    const int tid = threadIdx.x;
    const int lid = tid & 31;
    const int wm  = tid >> 5;
    const int qi  = (int)(gridDim.x - 1 - blockIdx.x);   // big blocks first
    const int h   = blockIdx.y;
    const int b   = blockIdx.z;
    const int q0  = qi * 128;
    const size_t baseE = (size_t)(b * HH + h) * TT * DD;

    const int a_r  = (lid & 7) + ((lid >> 3) & 1) * 8;
    const int a_cb = (lid >> 4) * 16;
    const int b_r  = ((lid >> 4) & 1) * 8 + (lid & 7);
    const int b_cb = ((lid >> 3) & 1) * 16;

    // ---- Stage Q (hi/lo fp16) via cp.async into buf0 area ----
    #pragma unroll
    for (int p = 0; p < 8; ++p) {
        int idx = p * 256 + tid;          // 0..2047
        int sub = idx >> 10;              // 0 = qh, 1 = ql
        int r   = (idx >> 3) & 127;
        int c   = idx & 7;
        uint32_t dst = sb + sub * 18432 + r * AP + c * 16;
        const __half* g = sub ? g_ql : g_qh;
        const char* src = (const char*)g +
            (baseE + (size_t)(q0 + r) * DD + c * 8) * 2;
        CP16(dst, src);
    }
    CP_COMMIT();
    CP_WAIT(0);
    __syncthreads();

    uint32_t qh[4][4], ql[4][4];
    #pragma unroll
    for (int ks = 0; ks < 4; ++ks) {
        uint32_t ra = (wm * 16 + a_r) * AP + a_cb + ks * 32;
        ldsm_x4(qh[ks][0], qh[ks][1], qh[ks][2], qh[ks][3], sb + 0 + ra);
        ldsm_x4(ql[ks][0], ql[ks][1], ql[ks][2], ql[ks][3], sb + 18432 + ra);
    }
    __syncthreads();

    float o[8][4];
    #pragma unroll
    for (int i = 0; i < 8; i++)
        #pragma unroll
        for (int j = 0; j < 4; j++) o[i][j] = 0.f;
    float m0 = -1e30f, m1 = -1e30f, l0 = 0.f, l1 = 0.f;

    const int row_min = q0 + wm * 16;
    const int r0g = row_min + (lid >> 2);
    const int col_e = (lid & 3) * 2;
    const float SC = 0.125f * 1.44269504f;   // 1/sqrt(D) * log2(e)

    auto issue = [&](int j) {
        const uint32_t s0 = sb + (j % 3) * ABUF;
        #pragma unroll
        for (int p = 0; p < 8; ++p) {
            int idx = p * 256 + tid;      // 0..2047
            int sub = idx >> 9;           // 0 Kh, 1 Kl, 2 Vh, 3 Vl
            int r   = (idx >> 3) & 63;
            int c   = idx & 7;
            const __half* g = (sub == 0) ? g_kh : (sub == 1) ? g_kl
                            : (sub == 2) ? g_vh : g_vl;
            uint32_t dst = s0 + sub * ATILE + r * AP + c * 16;
            const char* src = (const char*)g +
                (baseE + (size_t)(j * 64 + r) * DD + c * 8) * 2;
            CP16(dst, src);
        }
        CP_COMMIT();
    };

    const int ntiles = 2 * qi + 2;        // >= 2 always
    issue(0);
    issue(1);

    for (int j = 0; j < ntiles; ++j) {
        if (j + 1 < ntiles) { CP_WAIT(1); } else { CP_WAIT(0); }
        __syncthreads();
        if (j + 2 < ntiles) issue(j + 2);

        const uint32_t bufb = sb + (j % 3) * ABUF;

        // ---- S = Q K^T (3-term fp16 split) ----
        float s[8][4];
        #pragma unroll
        for (int i = 0; i < 8; i++)
            #pragma unroll
            for (int q = 0; q < 4; q++) s[i][q] = 0.f;

        #pragma unroll
        for (int ks = 0; ks < 4; ++ks) {
            uint32_t bh[4][4], bl[4][4];
            #pragma unroll
            for (int ng = 0; ng < 4; ++ng) {
                uint32_t rb = (ng * 16 + b_r) * AP + b_cb + ks * 32;
                ldsm_x4(bh[ng][0], bh[ng][1], bh[ng][2], bh[ng][3], bufb + 0 * ATILE + rb);
                ldsm_x4(bl[ng][0], bl[ng][1], bl[ng][2], bl[ng][3], bufb + 1 * ATILE + rb);
            }
            #pragma unroll
            for (int nt = 0; nt < 8; ++nt) {
                uint32_t b0h = bh[nt >> 1][(nt & 1) * 2];
                uint32_t b1h = bh[nt >> 1][(nt & 1) * 2 + 1];
                uint32_t b0l = bl[nt >> 1][(nt & 1) * 2];
                uint32_t b1l = bl[nt >> 1][(nt & 1) * 2 + 1];
                mma_f16(s[nt], qh[ks][0], qh[ks][1], qh[ks][2], qh[ks][3], b0h, b1h);
                mma_f16(s[nt], qh[ks][0], qh[ks][1], qh[ks][2], qh[ks][3], b0l, b1l);
                mma_f16(s[nt], ql[ks][0], ql[ks][1], ql[ks][2], ql[ks][3], b0h, b1h);
            }
        }

        // ---- scale + causal mask ----
        #pragma unroll
        for (int nt = 0; nt < 8; ++nt) {
            s[nt][0] *= SC; s[nt][1] *= SC; s[nt][2] *= SC; s[nt][3] *= SC;
        }
        if (j * 64 + 63 > row_min) {
            #pragma unroll
            for (int nt = 0; nt < 8; ++nt) {
                int c0 = j * 64 + nt * 8 + col_e;
                if (c0     > r0g)     s[nt][0] = -1e30f;
                if (c0 + 1 > r0g)     s[nt][1] = -1e30f;
                if (c0     > r0g + 8) s[nt][2] = -1e30f;
                if (c0 + 1 > r0g + 8) s[nt][3] = -1e30f;
            }
        }

        // ---- online softmax (base-2, in fragments) ----
        float mx0 = -1e30f, mx1 = -1e30f;
        #pragma unroll
        for (int nt = 0; nt < 8; ++nt) {
            mx0 = fmaxf(mx0, fmaxf(s[nt][0], s[nt][1]));
            mx1 = fmaxf(mx1, fmaxf(s[nt][2], s[nt][3]));
        }
        mx0 = fmaxf(mx0, __shfl_xor_sync(0xffffffffu, mx0, 1));
        mx0 = fmaxf(mx0, __shfl_xor_sync(0xffffffffu, mx0, 2));
        mx1 = fmaxf(mx1, __shfl_xor_sync(0xffffffffu, mx1, 1));
        mx1 = fmaxf(mx1, __shfl_xor_sync(0xffffffffu, mx1, 2));
        float m0n = fmaxf(m0, mx0), m1n = fmaxf(m1, mx1);
        float f0 = exp2f(m0 - m0n), f1 = exp2f(m1 - m1n);
        m0 = m0n; m1 = m1n;

        float sum0 = 0.f, sum1 = 0.f;
        #pragma unroll
        for (int nt = 0; nt < 8; ++nt) {
            s[nt][0] = exp2f(s[nt][0] - m0n);
            s[nt][1] = exp2f(s[nt][1] - m0n);
            s[nt][2] = exp2f(s[nt][2] - m1n);
            s[nt][3] = exp2f(s[nt][3] - m1n);
            sum0 += s[nt][0] + s[nt][1];
            sum1 += s[nt][2] + s[nt][3];
        }
        sum0 += __shfl_xor_sync(0xffffffffu, sum0, 1);
        sum0 += __shfl_xor_sync(0xffffffffu, sum0, 2);
        sum1 += __shfl_xor_sync(0xffffffffu, sum1, 1);
        sum1 += __shfl_xor_sync(0xffffffffu, sum1, 2);
        l0 = l0 * f0 + sum0;
        l1 = l1 * f1 + sum1;

        #pragma unroll
        for (int nt = 0; nt < 8; ++nt) {
            o[nt][0] *= f0; o[nt][1] *= f0;
            o[nt][2] *= f1; o[nt][3] *= f1;
        }

        // ---- O += P V (3-term fp16 split; P split in registers) ----
        #pragma unroll
        for (int ks = 0; ks < 4; ++ks) {
            uint32_t pah[4], pal[4];
            split2h(s[2*ks    ][0], s[2*ks    ][1], pah[0], pal[0]);
            split2h(s[2*ks    ][2], s[2*ks    ][3], pah[1], pal[1]);
            split2h(s[2*ks + 1][0], s[2*ks + 1][1], pah[2], pal[2]);
            split2h(s[2*ks + 1][2], s[2*ks + 1][3], pah[3], pal[3]);
            #pragma unroll
            for (int dg = 0; dg < 4; ++dg) {
                uint32_t vh[4], vl[4];
                uint32_t rv = (ks * 16 + a_r) * AP + dg * 32 + a_cb;
                ldsm_x4_t(vh[0], vh[1], vh[2], vh[3], bufb + 2 * ATILE + rv);
                ldsm_x4_t(vl[0], vl[1], vl[2], vl[3], bufb + 3 * ATILE + rv);
                int nt = dg * 2;
                mma_f16(o[nt],     pah[0], pah[1], pah[2], pah[3], vh[0], vh[1]);
                mma_f16(o[nt],     pah[0], pah[1], pah[2], pah[3], vl[0], vl[1]);
                mma_f16(o[nt],     pal[0], pal[1], pal[2], pal[3], vh[0], vh[1]);
                mma_f16(o[nt + 1], pah[0], pah[1], pah[2], pah[3], vh[2], vh[3]);
                mma_f16(o[nt + 1], pah[0], pah[1], pah[2], pah[3], vl[2], vl[3]);
                mma_f16(o[nt + 1], pal[0], pal[1], pal[2], pal[3], vh[2], vh[3]);
            }
        }
        __syncthreads();
    }

    // ---- finalize: divide by l, write [B,T,C] fp32 ----
    {
        float inv0 = 1.0f / l0, inv1 = 1.0f / l1;
        #pragma unroll
        for (int nt = 0; nt < 8; ++nt) {
            int c = h * 64 + nt * 8 + col_e;
            float2 v0 = make_float2(o[nt][0] * inv0, o[nt][1] * inv0);
            float2 v1 = make_float2(o[nt][2] * inv1, o[nt][3] * inv1);
            *(float2*)(out + (size_t)(b * TT + r0g)     * CC + c) = v0;
            *(float2*)(out + (size_t)(b * TT + r0g + 8) * CC + c) = v1;
        }
    }
}

// ---------------------------------------------------------------------------
extern "C" void kernel_launch(void* const* d_in, const int* in_sizes, int n_in,
                              void* d_out, int out_size)
{
    const float* x    = (const float*)d_in[0];   // [2,2048,1024]
    const float* w    = (const float*)d_in[1];   // [1024,3072]
    const float* bias = (const float*)d_in[2];   // [3072]
    float* out = (float*)d_out;                  // [2,2048,1024]

    cudaFuncSetAttribute((const void*)qkv_gemm,
                         cudaFuncAttributeMaxDynamicSharedMemorySize, GEMM_SMEM);
    cudaFuncSetAttribute((const void*)attn_mma,
                         cudaFuncAttributeMaxDynamicSharedMemorySize, ATTN_SMEM);

    convert_x<<<MM * CC / 1024, 256>>>(x);
    convert_w<<<dim3(N3 / 128, CC / 16), 128>>>(w);
    qkv_gemm<<<dim3(N3 / 128, MM / 128), 256, GEMM_SMEM>>>(bias);
    attn_mma<<<dim3(TT / 128, HH, BB), 256, ATTN_SMEM>>>(out);
}

// round 8
// speedup vs baseline: 4.0782x; 1.2413x over previous
#include <cuda_runtime.h>
#include <cuda_fp16.h>
#include <cstdint>
#include <math.h>

// Problem constants
#define BB  2
#define TT  2048
#define CC  1024
#define HH  16
#define DD  64
#define N3  (3*CC)      // 3072
#define MM  (BB*TT)     // 4096

// Pre-converted operands (device globals: allocation-free)
__device__ __half g_xh[MM*CC];           // x in fp16 (hi only), [m][k]
__device__ __half g_wh[N3*CC];           // w hi, K-major [n][k]
__device__ __half g_wl[N3*CC];           // w lo residual, K-major [n][k]
// Q,K,V split fp16 pairs in [B,H,T,D]
__device__ __half g_qh[BB*HH*TT*DD];
__device__ __half g_ql[BB*HH*TT*DD];
__device__ __half g_kh[BB*HH*TT*DD];
__device__ __half g_kl[BB*HH*TT*DD];
__device__ __half g_vh[BB*HH*TT*DD];
__device__ __half g_vl[BB*HH*TT*DD];     // written, no longer read (PV 1-term)

// ===========================================================================
// Portable PTX helpers (sm_80+)
// ===========================================================================
__device__ __forceinline__ uint32_t smem_u32(const void* p) {
    uint32_t a;
    asm("{ .reg .u64 t; cvta.to.shared.u64 t, %1; cvt.u32.u64 %0, t; }"
        : "=r"(a) : "l"(p));
    return a;
}

__device__ __forceinline__ void ldsm_x4(uint32_t& r0, uint32_t& r1,
                                        uint32_t& r2, uint32_t& r3,
                                        uint32_t addr) {
    asm volatile("ldmatrix.sync.aligned.m8n8.x4.shared.b16 {%0,%1,%2,%3}, [%4];"
                 : "=r"(r0), "=r"(r1), "=r"(r2), "=r"(r3) : "r"(addr));
}

__device__ __forceinline__ void ldsm_x4_t(uint32_t& r0, uint32_t& r1,
                                          uint32_t& r2, uint32_t& r3,
                                          uint32_t addr) {
    asm volatile("ldmatrix.sync.aligned.m8n8.x4.trans.shared.b16 {%0,%1,%2,%3}, [%4];"
                 : "=r"(r0), "=r"(r1), "=r"(r2), "=r"(r3) : "r"(addr));
}

__device__ __forceinline__ void mma_f16(float* c,
                                        uint32_t a0, uint32_t a1,
                                        uint32_t a2, uint32_t a3,
                                        uint32_t b0, uint32_t b1) {
    asm volatile(
        "mma.sync.aligned.m16n8k16.row.col.f32.f16.f16.f32 "
        "{%0,%1,%2,%3}, {%4,%5,%6,%7}, {%8,%9}, {%0,%1,%2,%3};"
        : "+f"(c[0]), "+f"(c[1]), "+f"(c[2]), "+f"(c[3])
        : "r"(a0), "r"(a1), "r"(a2), "r"(a3), "r"(b0), "r"(b1));
}

// pack 2 fp32 -> rn-fp16x2
__device__ __forceinline__ uint32_t pack_h2(float v0, float v1) {
    uint32_t h;
    asm("cvt.rn.f16x2.f32 %0, %1, %2;" : "=r"(h) : "f"(v1), "f"(v0));
    return h;
}

// split fp32 -> (rn-fp16 pair, fp16 residual pair)
__device__ __forceinline__ void split2h(float v0, float v1,
                                        uint32_t& h, uint32_t& l) {
    asm("cvt.rn.f16x2.f32 %0, %1, %2;" : "=r"(h) : "f"(v1), "f"(v0));
    float h0, h1;
    asm("{ .reg .f16 a, b;\n\t"
        "  mov.b32 {a, b}, %2;\n\t"
        "  cvt.f32.f16 %0, a;\n\t"
        "  cvt.f32.f16 %1, b; }"
        : "=f"(h0), "=f"(h1) : "r"(h));
    asm("cvt.rn.f16x2.f32 %0, %1, %2;" : "=r"(l) : "f"(v1 - h1), "f"(v0 - h0));
}

#define CP16(dst, src) \
    asm volatile("cp.async.cg.shared.global [%0], [%1], 16;" \
        :: "r"(dst), "l"(src) : "memory")
#define CP_COMMIT() asm volatile("cp.async.commit_group;" ::: "memory")
#define CP_WAIT(n)  asm volatile("cp.async.wait_group %0;" :: "n"(n) : "memory")

#define HONES 0x3C003C00u   // fp16 {1.0, 1.0}

// ===========================================================================
// Kernel 0a: x fp32 -> fp16 (hi only)
// ===========================================================================
__global__ __launch_bounds__(256)
void convert_x(const float* __restrict__ x)
{
    int i = (blockIdx.x * 256 + threadIdx.x) * 4;
    float4 v = *(const float4*)(x + i);
    uint2 o = make_uint2(pack_h2(v.x, v.y), pack_h2(v.z, v.w));
    *(uint2*)((char*)g_xh + (size_t)i * 2) = o;
}

// ===========================================================================
// Kernel 0b: w [k][n] fp32 -> (wh, wl) fp16 K-major [n][k]
// ===========================================================================
__global__ __launch_bounds__(128)
void convert_w(const float* __restrict__ w)
{
    int n  = blockIdx.x * 128 + threadIdx.x;
    int k0 = blockIdx.y * 16;
    const float* wp = w + (size_t)k0 * N3 + n;
    float v[16];
    #pragma unroll
    for (int q = 0; q < 16; ++q) v[q] = wp[(size_t)q * N3];
    uint32_t hi[8], lo[8];
    #pragma unroll
    for (int q = 0; q < 8; ++q) split2h(v[2*q], v[2*q+1], hi[q], lo[q]);
    size_t off = ((size_t)n * CC + k0) * 2;
    *(uint4*)((char*)g_wh + off)      = make_uint4(hi[0], hi[1], hi[2], hi[3]);
    *(uint4*)((char*)g_wh + off + 16) = make_uint4(hi[4], hi[5], hi[6], hi[7]);
    *(uint4*)((char*)g_wl + off)      = make_uint4(lo[0], lo[1], lo[2], lo[3]);
    *(uint4*)((char*)g_wl + off + 16) = make_uint4(lo[4], lo[5], lo[6], lo[7]);
}

// ===========================================================================
// Kernel 1: QKV GEMM, fp16 2-term (Ah*Bh + Ah*Bl). CTA tile M=256 N=128
// (512 threads), BK=64, cp.async triple buffer, one barrier per iteration.
// L2 traffic 576MB (vs 960MB at 128x128).
// ===========================================================================
#define GP     144
#define GT128  (128*GP)        // 18432
#define GSTAGE (4*GT128)       // A(2) + Bh(1) + Bl(1) = 73728
#define GEMM_SMEM (3*GSTAGE)   // 221184

__global__ __launch_bounds__(512, 1)
void qkv_gemm(const float* __restrict__ bias)
{
    extern __shared__ char smem[];
    const uint32_t sb = smem_u32(smem);

    const int tid = threadIdx.x;
    const int lid = tid & 31;
    const int wid = tid >> 5;          // 0..15
    const int wm  = wid & 7;           // 8 m-groups x 32 rows = 256
    const int wn  = wid >> 3;          // 2 n-groups x 64 cols
    const int n0  = blockIdx.x * 128;
    const int m0  = blockIdx.y * 256;

    const int a_r  = (lid & 7) + ((lid >> 3) & 1) * 8;
    const int a_cb = (lid >> 4) * 16;
    const int b_r  = ((lid >> 4) & 1) * 8 + (lid & 7);
    const int b_cb = ((lid >> 3) & 1) * 16;

    float acc[2][8][4];
    #pragma unroll
    for (int i = 0; i < 2; i++)
        #pragma unroll
        for (int j = 0; j < 8; j++)
            #pragma unroll
            for (int q = 0; q < 4; q++) acc[i][j][q] = 0.f;

    const int c_row = tid >> 3;        // 0..63
    const int c_c   = tid & 7;         // 16B chunk

    auto issue = [&](int it) {
        const int k0 = it * 64;
        const uint32_t s0 = sb + (it % 3) * GSTAGE;
        #pragma unroll
        for (int p = 0; p < 4; ++p) {
            int row = c_row + p * 64;  // 0..255
            CP16(s0 + row * GP + c_c * 16,
                 (const char*)g_xh + (((size_t)(m0 + row)) * CC + k0 + c_c * 8) * 2);
        }
        #pragma unroll
        for (int p = 0; p < 2; ++p) {
            int row = c_row + p * 64;  // 0..127
            size_t go = (((size_t)(n0 + row)) * CC + k0 + c_c * 8) * 2;
            CP16(s0 + 2 * GT128 + row * GP + c_c * 16, (const char*)g_wh + go);
            CP16(s0 + 3 * GT128 + row * GP + c_c * 16, (const char*)g_wl + go);
        }
        CP_COMMIT();
    };

    auto compute = [&](int buf) {
        const uint32_t A  = sb + buf * GSTAGE;
        const uint32_t Bh = A + 2 * GT128;
        const uint32_t Bl = A + 3 * GT128;
        #pragma unroll
        for (int ks = 0; ks < 4; ++ks) {
            const int kb = ks * 32;
            uint32_t ah[2][4], bh[4][4], bl[4][4];
            #pragma unroll
            for (int mt = 0; mt < 2; ++mt) {
                uint32_t ra = (wm * 32 + mt * 16 + a_r) * GP + a_cb + kb;
                ldsm_x4(ah[mt][0], ah[mt][1], ah[mt][2], ah[mt][3], A + ra);
            }
            #pragma unroll
            for (int bt = 0; bt < 4; ++bt) {
                uint32_t rb = (wn * 64 + bt * 16 + b_r) * GP + b_cb + kb;
                ldsm_x4(bh[bt][0], bh[bt][1], bh[bt][2], bh[bt][3], Bh + rb);
                ldsm_x4(bl[bt][0], bl[bt][1], bl[bt][2], bl[bt][3], Bl + rb);
            }
            #pragma unroll
            for (int mt = 0; mt < 2; ++mt)
                #pragma unroll
                for (int nt = 0; nt < 8; ++nt) {
                    uint32_t b0h = bh[nt >> 1][(nt & 1) * 2];
                    uint32_t b1h = bh[nt >> 1][(nt & 1) * 2 + 1];
                    uint32_t b0l = bl[nt >> 1][(nt & 1) * 2];
                    uint32_t b1l = bl[nt >> 1][(nt & 1) * 2 + 1];
                    mma_f16(acc[mt][nt], ah[mt][0], ah[mt][1], ah[mt][2], ah[mt][3], b0h, b1h);
                    mma_f16(acc[mt][nt], ah[mt][0], ah[mt][1], ah[mt][2], ah[mt][3], b0l, b1l);
                }
        }
    };

    issue(0);
    issue(1);
    for (int it = 0; it < 16; ++it) {
        if (it < 15) { CP_WAIT(1); } else { CP_WAIT(0); }
        __syncthreads();
        if (it + 2 < 16) issue(it + 2);
        compute(it % 3);
    }

    // Epilogue: +bias, split fp16 hi/lo, scatter to q/k/v [B,H,T,D]
    {
        const int n_warp = n0 + wn * 64;
        const int which  = n_warp >> 10;
        const int ccn    = n_warp & (CC - 1);
        const int h      = ccn >> 6;
        __half* dh = (which == 0) ? g_qh : ((which == 1) ? g_kh : g_vh);
        __half* dl = (which == 0) ? g_ql : ((which == 1) ? g_kl : g_vl);

        #pragma unroll
        for (int mt = 0; mt < 2; ++mt) {
            int gm = m0 + wm * 32 + mt * 16 + (lid >> 2);
            #pragma unroll
            for (int half = 0; half < 2; ++half) {
                int gmr = gm + half * 8;
                int bb = gmr >> 11;
                int t  = gmr & (TT - 1);
                size_t rowhw = ((size_t)(bb * HH + h) * TT + t) * DD;
                #pragma unroll
                for (int nt = 0; nt < 8; ++nt) {
                    int d = nt * 8 + (lid & 3) * 2;
                    float2 bv = *(const float2*)(bias + n_warp + d);
                    float ox = acc[mt][nt][half * 2 + 0] + bv.x;
                    float oy = acc[mt][nt][half * 2 + 1] + bv.y;
                    uint32_t hi, lo;
                    split2h(ox, oy, hi, lo);
                    *(uint32_t*)((char*)dh + (rowhw + d) * 2) = hi;
                    *(uint32_t*)((char*)dl + (rowhw + d) * 2) = lo;
                }
            }
        }
    }
}

// ===========================================================================
// Kernel 2: causal flash attention. S = 3-term fp16 split (near-exact);
// PV = 1-term (P,V fp16 hi-only; denominator from same rounded P via
// ones-column MMA so P rounding cancels). cp.async triple buffer.
// ===========================================================================
#define AP 144
#define ATILE (64*AP)        // 9216
#define ABUF  (3*ATILE)      // 27648: Kh, Kl, Vh
#define ATTN_SMEM (3*ABUF)   // 82944

__global__ __launch_bounds__(256, 1)
void attn_mma(float* __restrict__ out)
{
    extern __shared__ char smem[];
    const uint32_t sb = smem_u32(smem);

    const int tid = threadIdx.x;
    const int lid = tid & 31;
    const int wm  = tid >> 5;
    const int qi  = (int)(gridDim.x - 1 - blockIdx.x);   // big blocks first
    const int h   = blockIdx.y;
    const int b   = blockIdx.z;
    const int q0  = qi * 128;
    const size_t baseE = (size_t)(b * HH + h) * TT * DD;

    const int a_r  = (lid & 7) + ((lid >> 3) & 1) * 8;
    const int a_cb = (lid >> 4) * 16;
    const int b_r  = ((lid >> 4) & 1) * 8 + (lid & 7);
    const int b_cb = ((lid >> 3) & 1) * 16;

    // ---- Stage Q (hi/lo fp16) via cp.async into buffer region (pre-KV) ----
    #pragma unroll
    for (int p = 0; p < 8; ++p) {
        int idx = p * 256 + tid;          // 0..2047
        int sub = idx >> 10;              // 0 = qh, 1 = ql
        int r   = (idx >> 3) & 127;
        int c   = idx & 7;
        uint32_t dst = sb + sub * 18432 + r * AP + c * 16;
        const __half* g = sub ? g_ql : g_qh;
        const char* src = (const char*)g +
            (baseE + (size_t)(q0 + r) * DD + c * 8) * 2;
        CP16(dst, src);
    }
    CP_COMMIT();
    CP_WAIT(0);
    __syncthreads();

    uint32_t qh[4][4], ql[4][4];
    #pragma unroll
    for (int ks = 0; ks < 4; ++ks) {
        uint32_t ra = (wm * 16 + a_r) * AP + a_cb + ks * 32;
        ldsm_x4(qh[ks][0], qh[ks][1], qh[ks][2], qh[ks][3], sb + 0 + ra);
        ldsm_x4(ql[ks][0], ql[ks][1], ql[ks][2], ql[ks][3], sb + 18432 + ra);
    }
    __syncthreads();

    float o[8][4];
    #pragma unroll
    for (int i = 0; i < 8; i++)
        #pragma unroll
        for (int j = 0; j < 4; j++) o[i][j] = 0.f;
    float lacc[4] = {0.f, 0.f, 0.f, 0.f};
    float m0 = -1e30f, m1 = -1e30f;

    const int row_min = q0 + wm * 16;
    const int r0g = row_min + (lid >> 2);
    const int col_e = (lid & 3) * 2;
    const float SC = 0.125f * 1.44269504f;   // 1/sqrt(D) * log2(e)

    auto issue = [&](int j) {
        const uint32_t s0 = sb + (j % 3) * ABUF;
        #pragma unroll
        for (int p = 0; p < 6; ++p) {
            int idx = p * 256 + tid;      // 0..1535
            int sub = idx >> 9;           // 0 Kh, 1 Kl, 2 Vh
            int r   = (idx >> 3) & 63;
            int c   = idx & 7;
            const __half* g = (sub == 0) ? g_kh : (sub == 1) ? g_kl : g_vh;
            uint32_t dst = s0 + sub * ATILE + r * AP + c * 16;
            const char* src = (const char*)g +
                (baseE + (size_t)(j * 64 + r) * DD + c * 8) * 2;
            CP16(dst, src);
        }
        CP_COMMIT();
    };

    const int ntiles = 2 * qi + 2;        // >= 2 always
    issue(0);
    issue(1);

    for (int j = 0; j < ntiles; ++j) {
        if (j + 1 < ntiles) { CP_WAIT(1); } else { CP_WAIT(0); }
        __syncthreads();
        if (j + 2 < ntiles) issue(j + 2);

        const uint32_t bufb = sb + (j % 3) * ABUF;

        // ---- S = Q K^T (3-term fp16 split) ----
        float s[8][4];
        #pragma unroll
        for (int i = 0; i < 8; i++)
            #pragma unroll
            for (int q = 0; q < 4; q++) s[i][q] = 0.f;

        #pragma unroll
        for (int ks = 0; ks < 4; ++ks) {
            uint32_t bh[4][4], bl[4][4];
            #pragma unroll
            for (int ng = 0; ng < 4; ++ng) {
                uint32_t rb = (ng * 16 + b_r) * AP + b_cb + ks * 32;
                ldsm_x4(bh[ng][0], bh[ng][1], bh[ng][2], bh[ng][3], bufb + 0 * ATILE + rb);
                ldsm_x4(bl[ng][0], bl[ng][1], bl[ng][2], bl[ng][3], bufb + 1 * ATILE + rb);
            }
            #pragma unroll
            for (int nt = 0; nt < 8; ++nt) {
                uint32_t b0h = bh[nt >> 1][(nt & 1) * 2];
                uint32_t b1h = bh[nt >> 1][(nt & 1) * 2 + 1];
                uint32_t b0l = bl[nt >> 1][(nt & 1) * 2];
                uint32_t b1l = bl[nt >> 1][(nt & 1) * 2 + 1];
                mma_f16(s[nt], qh[ks][0], qh[ks][1], qh[ks][2], qh[ks][3], b0h, b1h);
                mma_f16(s[nt], qh[ks][0], qh[ks][1], qh[ks][2], qh[ks][3], b0l, b1l);
                mma_f16(s[nt], ql[ks][0], ql[ks][1], ql[ks][2], ql[ks][3], b0h, b1h);
            }
        }

        // ---- scale + causal mask ----
        #pragma unroll
        for (int nt = 0; nt < 8; ++nt) {
            s[nt][0] *= SC; s[nt][1] *= SC; s[nt][2] *= SC; s[nt][3] *= SC;
        }
        if (j * 64 + 63 > row_min) {
            #pragma unroll
            for (int nt = 0; nt < 8; ++nt) {
                int c0 = j * 64 + nt * 8 + col_e;
                if (c0     > r0g)     s[nt][0] = -1e30f;
                if (c0 + 1 > r0g)     s[nt][1] = -1e30f;
                if (c0     > r0g + 8) s[nt][2] = -1e30f;
                if (c0 + 1 > r0g + 8) s[nt][3] = -1e30f;
            }
        }

        // ---- online softmax (base-2, in fragments) ----
        float mx0 = -1e30f, mx1 = -1e30f;
        #pragma unroll
        for (int nt = 0; nt < 8; ++nt) {
            mx0 = fmaxf(mx0, fmaxf(s[nt][0], s[nt][1]));
            mx1 = fmaxf(mx1, fmaxf(s[nt][2], s[nt][3]));
        }
        mx0 = fmaxf(mx0, __shfl_xor_sync(0xffffffffu, mx0, 1));
        mx0 = fmaxf(mx0, __shfl_xor_sync(0xffffffffu, mx0, 2));
        mx1 = fmaxf(mx1, __shfl_xor_sync(0xffffffffu, mx1, 1));
        mx1 = fmaxf(mx1, __shfl_xor_sync(0xffffffffu, mx1, 2));
        float m0n = fmaxf(m0, mx0), m1n = fmaxf(m1, mx1);
        float f0 = exp2f(m0 - m0n), f1 = exp2f(m1 - m1n);
        m0 = m0n; m1 = m1n;

        #pragma unroll
        for (int nt = 0; nt < 8; ++nt) {
            s[nt][0] = exp2f(s[nt][0] - m0n);
            s[nt][1] = exp2f(s[nt][1] - m0n);
            s[nt][2] = exp2f(s[nt][2] - m1n);
            s[nt][3] = exp2f(s[nt][3] - m1n);
        }

        // rescale running accumulators (o and the MMA-computed row sums)
        #pragma unroll
        for (int nt = 0; nt < 8; ++nt) {
            o[nt][0] *= f0; o[nt][1] *= f0;
            o[nt][2] *= f1; o[nt][3] *= f1;
        }
        lacc[0] *= f0; lacc[1] *= f0; lacc[2] *= f1; lacc[3] *= f1;

        // ---- O += P V (1-term: P,V fp16 hi-only) + l row-sum via ones-MMA ----
        #pragma unroll
        for (int ks = 0; ks < 4; ++ks) {
            uint32_t pa[4];
            pa[0] = pack_h2(s[2*ks    ][0], s[2*ks    ][1]);
            pa[1] = pack_h2(s[2*ks    ][2], s[2*ks    ][3]);
            pa[2] = pack_h2(s[2*ks + 1][0], s[2*ks + 1][1]);
            pa[3] = pack_h2(s[2*ks + 1][2], s[2*ks + 1][3]);
            mma_f16(lacc, pa[0], pa[1], pa[2], pa[3], HONES, HONES);
            #pragma unroll
            for (int dg = 0; dg < 4; ++dg) {
                uint32_t vh[4];
                uint32_t rv = (ks * 16 + a_r) * AP + dg * 32 + a_cb;
                ldsm_x4_t(vh[0], vh[1], vh[2], vh[3], bufb + 2 * ATILE + rv);
                int nt = dg * 2;
                mma_f16(o[nt],     pa[0], pa[1], pa[2], pa[3], vh[0], vh[1]);
                mma_f16(o[nt + 1], pa[0], pa[1], pa[2], pa[3], vh[2], vh[3]);
            }
        }
        __syncthreads();
    }

    // ---- finalize: divide by l, write [B,T,C] fp32 ----
    {
        float inv0 = 1.0f / lacc[0], inv1 = 1.0f / lacc[2];
        #pragma unroll
        for (int nt = 0; nt < 8; ++nt) {
            int c = h * 64 + nt * 8 + col_e;
            float2 v0 = make_float2(o[nt][0] * inv0, o[nt][1] * inv0);
            float2 v1 = make_float2(o[nt][2] * inv1, o[nt][3] * inv1);
            *(float2*)(out + (size_t)(b * TT + r0g)     * CC + c) = v0;
            *(float2*)(out + (size_t)(b * TT + r0g + 8) * CC + c) = v1;
        }
    }
}

// ---------------------------------------------------------------------------
extern "C" void kernel_launch(void* const* d_in, const int* in_sizes, int n_in,
                              void* d_out, int out_size)
{
    const float* x    = (const float*)d_in[0];   // [2,2048,1024]
    const float* w    = (const float*)d_in[1];   // [1024,3072]
    const float* bias = (const float*)d_in[2];   // [3072]
    float* out = (float*)d_out;                  // [2,2048,1024]

    cudaFuncSetAttribute((const void*)qkv_gemm,
                         cudaFuncAttributeMaxDynamicSharedMemorySize, GEMM_SMEM);
    cudaFuncSetAttribute((const void*)attn_mma,
                         cudaFuncAttributeMaxDynamicSharedMemorySize, ATTN_SMEM);

    convert_x<<<MM * CC / 1024, 256>>>(x);
    convert_w<<<dim3(N3 / 128, CC / 16), 128>>>(w);
    qkv_gemm<<<dim3(N3 / 128, MM / 256), 512, GEMM_SMEM>>>(bias);
    attn_mma<<<dim3(TT / 128, HH, BB), 256, ATTN_SMEM>>>(out);
}

// round 9
// speedup vs baseline: 4.1162x; 1.0093x over previous
#include <cuda_runtime.h>
#include <cuda_fp16.h>
#include <cstdint>
#include <math.h>

// Problem constants
#define BB  2
#define TT  2048
#define CC  1024
#define HH  16
#define DD  64
#define N3  (3*CC)      // 3072
#define MM  (BB*TT)     // 4096

// Pre-converted operands (device globals: allocation-free)
__device__ __half g_xh[MM*CC];           // x in fp16 (hi only), [m][k]
__device__ __half g_wh[N3*CC];           // w hi, K-major [n][k]
__device__ __half g_wl[N3*CC];           // w lo residual, K-major [n][k]
// Q,K,V split fp16 pairs in [B,H,T,D]  (Q pre-scaled by 0.125*log2e)
__device__ __half g_qh[BB*HH*TT*DD];
__device__ __half g_ql[BB*HH*TT*DD];
__device__ __half g_kh[BB*HH*TT*DD];
__device__ __half g_kl[BB*HH*TT*DD];
__device__ __half g_vh[BB*HH*TT*DD];
__device__ __half g_vl[BB*HH*TT*DD];     // written, no longer read (PV 1-term)

// ===========================================================================
// Portable PTX helpers (sm_80+)
// ===========================================================================
__device__ __forceinline__ uint32_t smem_u32(const void* p) {
    uint32_t a;
    asm("{ .reg .u64 t; cvta.to.shared.u64 t, %1; cvt.u32.u64 %0, t; }"
        : "=r"(a) : "l"(p));
    return a;
}

__device__ __forceinline__ void ldsm_x4(uint32_t& r0, uint32_t& r1,
                                        uint32_t& r2, uint32_t& r3,
                                        uint32_t addr) {
    asm volatile("ldmatrix.sync.aligned.m8n8.x4.shared.b16 {%0,%1,%2,%3}, [%4];"
                 : "=r"(r0), "=r"(r1), "=r"(r2), "=r"(r3) : "r"(addr));
}

__device__ __forceinline__ void ldsm_x4_t(uint32_t& r0, uint32_t& r1,
                                          uint32_t& r2, uint32_t& r3,
                                          uint32_t addr) {
    asm volatile("ldmatrix.sync.aligned.m8n8.x4.trans.shared.b16 {%0,%1,%2,%3}, [%4];"
                 : "=r"(r0), "=r"(r1), "=r"(r2), "=r"(r3) : "r"(addr));
}

__device__ __forceinline__ void mma_f16(float* c,
                                        uint32_t a0, uint32_t a1,
                                        uint32_t a2, uint32_t a3,
                                        uint32_t b0, uint32_t b1) {
    asm volatile(
        "mma.sync.aligned.m16n8k16.row.col.f32.f16.f16.f32 "
        "{%0,%1,%2,%3}, {%4,%5,%6,%7}, {%8,%9}, {%0,%1,%2,%3};"
        : "+f"(c[0]), "+f"(c[1]), "+f"(c[2]), "+f"(c[3])
        : "r"(a0), "r"(a1), "r"(a2), "r"(a3), "r"(b0), "r"(b1));
}

// pack 2 fp32 -> rn-fp16x2
__device__ __forceinline__ uint32_t pack_h2(float v0, float v1) {
    uint32_t h;
    asm("cvt.rn.f16x2.f32 %0, %1, %2;" : "=r"(h) : "f"(v1), "f"(v0));
    return h;
}

// split fp32 -> (rn-fp16 pair, fp16 residual pair)
__device__ __forceinline__ void split2h(float v0, float v1,
                                        uint32_t& h, uint32_t& l) {
    asm("cvt.rn.f16x2.f32 %0, %1, %2;" : "=r"(h) : "f"(v1), "f"(v0));
    float h0, h1;
    asm("{ .reg .f16 a, b;\n\t"
        "  mov.b32 {a, b}, %2;\n\t"
        "  cvt.f32.f16 %0, a;\n\t"
        "  cvt.f32.f16 %1, b; }"
        : "=f"(h0), "=f"(h1) : "r"(h));
    asm("cvt.rn.f16x2.f32 %0, %1, %2;" : "=r"(l) : "f"(v1 - h1), "f"(v0 - h0));
}

#define CP16(dst, src) \
    asm volatile("cp.async.cg.shared.global [%0], [%1], 16;" \
        :: "r"(dst), "l"(src) : "memory")
#define CP_COMMIT() asm volatile("cp.async.commit_group;" ::: "memory")
#define CP_WAIT(n)  asm volatile("cp.async.wait_group %0;" :: "n"(n) : "memory")

#define HONES 0x3C003C00u   // fp16 {1.0, 1.0}

// ===========================================================================
// Kernel 0a: x fp32 -> fp16 (hi only)
// ===========================================================================
__global__ __launch_bounds__(256)
void convert_x(const float* __restrict__ x)
{
    int i = (blockIdx.x * 256 + threadIdx.x) * 4;
    float4 v = *(const float4*)(x + i);
    uint2 o = make_uint2(pack_h2(v.x, v.y), pack_h2(v.z, v.w));
    *(uint2*)((char*)g_xh + (size_t)i * 2) = o;
}

// ===========================================================================
// Kernel 0b: w [k][n] fp32 -> (wh, wl) fp16 K-major [n][k]
// ===========================================================================
__global__ __launch_bounds__(128)
void convert_w(const float* __restrict__ w)
{
    int n  = blockIdx.x * 128 + threadIdx.x;
    int k0 = blockIdx.y * 16;
    const float* wp = w + (size_t)k0 * N3 + n;
    float v[16];
    #pragma unroll
    for (int q = 0; q < 16; ++q) v[q] = wp[(size_t)q * N3];
    uint32_t hi[8], lo[8];
    #pragma unroll
    for (int q = 0; q < 8; ++q) split2h(v[2*q], v[2*q+1], hi[q], lo[q]);
    size_t off = ((size_t)n * CC + k0) * 2;
    *(uint4*)((char*)g_wh + off)      = make_uint4(hi[0], hi[1], hi[2], hi[3]);
    *(uint4*)((char*)g_wh + off + 16) = make_uint4(hi[4], hi[5], hi[6], hi[7]);
    *(uint4*)((char*)g_wl + off)      = make_uint4(lo[0], lo[1], lo[2], lo[3]);
    *(uint4*)((char*)g_wl + off + 16) = make_uint4(lo[4], lo[5], lo[6], lo[7]);
}

// ===========================================================================
// Kernel 1: QKV GEMM, fp16 2-term (Ah*Bh + Ah*Bl). CTA tile M=256 N=128
// (512 threads), BK=64, cp.async triple buffer, one barrier per iteration.
// MMA passes split by term (acc reuse distance 16) to avoid RAW chains.
// ===========================================================================
#define GP     144
#define GT128  (128*GP)        // 18432
#define GSTAGE (4*GT128)       // A(2) + Bh(1) + Bl(1) = 73728
#define GEMM_SMEM (3*GSTAGE)   // 221184

__global__ __launch_bounds__(512, 1)
void qkv_gemm(const float* __restrict__ bias)
{
    extern __shared__ char smem[];
    const uint32_t sb = smem_u32(smem);

    const int tid = threadIdx.x;
    const int lid = tid & 31;
    const int wid = tid >> 5;          // 0..15
    const int wm  = wid & 7;           // 8 m-groups x 32 rows = 256
    const int wn  = wid >> 3;          // 2 n-groups x 64 cols
    const int n0  = blockIdx.x * 128;
    const int m0  = blockIdx.y * 256;

    const int a_r  = (lid & 7) + ((lid >> 3) & 1) * 8;
    const int a_cb = (lid >> 4) * 16;
    const int b_r  = ((lid >> 4) & 1) * 8 + (lid & 7);
    const int b_cb = ((lid >> 3) & 1) * 16;

    float acc[2][8][4];
    #pragma unroll
    for (int i = 0; i < 2; i++)
        #pragma unroll
        for (int j = 0; j < 8; j++)
            #pragma unroll
            for (int q = 0; q < 4; q++) acc[i][j][q] = 0.f;

    const int c_row = tid >> 3;        // 0..63
    const int c_c   = tid & 7;         // 16B chunk

    auto issue = [&](int it) {
        const int k0 = it * 64;
        const uint32_t s0 = sb + (it % 3) * GSTAGE;
        #pragma unroll
        for (int p = 0; p < 4; ++p) {
            int row = c_row + p * 64;  // 0..255
            CP16(s0 + row * GP + c_c * 16,
                 (const char*)g_xh + (((size_t)(m0 + row)) * CC + k0 + c_c * 8) * 2);
        }
        #pragma unroll
        for (int p = 0; p < 2; ++p) {
            int row = c_row + p * 64;  // 0..127
            size_t go = (((size_t)(n0 + row)) * CC + k0 + c_c * 8) * 2;
            CP16(s0 + 2 * GT128 + row * GP + c_c * 16, (const char*)g_wh + go);
            CP16(s0 + 3 * GT128 + row * GP + c_c * 16, (const char*)g_wl + go);
        }
        CP_COMMIT();
    };

    auto compute = [&](int buf) {
        const uint32_t A  = sb + buf * GSTAGE;
        const uint32_t Bh = A + 2 * GT128;
        const uint32_t Bl = A + 3 * GT128;
        #pragma unroll
        for (int ks = 0; ks < 4; ++ks) {
            const int kb = ks * 32;
            uint32_t ah[2][4], bh[4][4], bl[4][4];
            #pragma unroll
            for (int mt = 0; mt < 2; ++mt) {
                uint32_t ra = (wm * 32 + mt * 16 + a_r) * GP + a_cb + kb;
                ldsm_x4(ah[mt][0], ah[mt][1], ah[mt][2], ah[mt][3], A + ra);
            }
            #pragma unroll
            for (int bt = 0; bt < 4; ++bt) {
                uint32_t rb = (wn * 64 + bt * 16 + b_r) * GP + b_cb + kb;
                ldsm_x4(bh[bt][0], bh[bt][1], bh[bt][2], bh[bt][3], Bh + rb);
                ldsm_x4(bl[bt][0], bl[bt][1], bl[bt][2], bl[bt][3], Bl + rb);
            }
            // pass 1: all hi-B MMAs (16 independent accumulators)
            #pragma unroll
            for (int mt = 0; mt < 2; ++mt)
                #pragma unroll
                for (int nt = 0; nt < 8; ++nt)
                    mma_f16(acc[mt][nt], ah[mt][0], ah[mt][1], ah[mt][2], ah[mt][3],
                            bh[nt >> 1][(nt & 1) * 2], bh[nt >> 1][(nt & 1) * 2 + 1]);
            // pass 2: all lo-B MMAs
            #pragma unroll
            for (int mt = 0; mt < 2; ++mt)
                #pragma unroll
                for (int nt = 0; nt < 8; ++nt)
                    mma_f16(acc[mt][nt], ah[mt][0], ah[mt][1], ah[mt][2], ah[mt][3],
                            bl[nt >> 1][(nt & 1) * 2], bl[nt >> 1][(nt & 1) * 2 + 1]);
        }
    };

    issue(0);
    issue(1);
    for (int it = 0; it < 16; ++it) {
        if (it < 15) { CP_WAIT(1); } else { CP_WAIT(0); }
        __syncthreads();
        if (it + 2 < 16) issue(it + 2);
        compute(it % 3);
    }

    // Epilogue: +bias, (Q: fold softmax scale), split fp16 hi/lo, scatter
    {
        const int n_warp = n0 + wn * 64;
        const int which  = n_warp >> 10;
        const int ccn    = n_warp & (CC - 1);
        const int h      = ccn >> 6;
        __half* dh = (which == 0) ? g_qh : ((which == 1) ? g_kh : g_vh);
        __half* dl = (which == 0) ? g_ql : ((which == 1) ? g_kl : g_vl);
        const float qs = (which == 0) ? (0.125f * 1.44269504f) : 1.0f;

        #pragma unroll
        for (int mt = 0; mt < 2; ++mt) {
            int gm = m0 + wm * 32 + mt * 16 + (lid >> 2);
            #pragma unroll
            for (int half = 0; half < 2; ++half) {
                int gmr = gm + half * 8;
                int bb = gmr >> 11;
                int t  = gmr & (TT - 1);
                size_t rowhw = ((size_t)(bb * HH + h) * TT + t) * DD;
                #pragma unroll
                for (int nt = 0; nt < 8; ++nt) {
                    int d = nt * 8 + (lid & 3) * 2;
                    float2 bv = *(const float2*)(bias + n_warp + d);
                    float ox = (acc[mt][nt][half * 2 + 0] + bv.x) * qs;
                    float oy = (acc[mt][nt][half * 2 + 1] + bv.y) * qs;
                    uint32_t hi, lo;
                    split2h(ox, oy, hi, lo);
                    *(uint32_t*)((char*)dh + (rowhw + d) * 2) = hi;
                    *(uint32_t*)((char*)dl + (rowhw + d) * 2) = lo;
                }
            }
        }
    }
}

// ===========================================================================
// Kernel 2: causal flash attention. S = 3-term fp16 split (term-major MMA
// passes, acc reuse distance 8); PV = 1-term with ones-column row-sum MMA.
// Q pre-scaled at GEMM epilogue. cp.async triple buffer.
// ===========================================================================
#define AP 144
#define ATILE (64*AP)        // 9216
#define ABUF  (3*ATILE)      // 27648: Kh, Kl, Vh
#define ATTN_SMEM (3*ABUF)   // 82944

__global__ __launch_bounds__(256, 1)
void attn_mma(float* __restrict__ out)
{
    extern __shared__ char smem[];
    const uint32_t sb = smem_u32(smem);

    const int tid = threadIdx.x;
    const int lid = tid & 31;
    const int wm  = tid >> 5;
    const int qi  = (int)(gridDim.x - 1 - blockIdx.x);   // big blocks first
    const int h   = blockIdx.y;
    const int b   = blockIdx.z;
    const int q0  = qi * 128;
    const size_t baseE = (size_t)(b * HH + h) * TT * DD;

    const int a_r  = (lid & 7) + ((lid >> 3) & 1) * 8;
    const int a_cb = (lid >> 4) * 16;
    const int b_r  = ((lid >> 4) & 1) * 8 + (lid & 7);
    const int b_cb = ((lid >> 3) & 1) * 16;

    // ---- Stage Q (hi/lo fp16, pre-scaled) via cp.async ----
    #pragma unroll
    for (int p = 0; p < 8; ++p) {
        int idx = p * 256 + tid;          // 0..2047
        int sub = idx >> 10;              // 0 = qh, 1 = ql
        int r   = (idx >> 3) & 127;
        int c   = idx & 7;
        uint32_t dst = sb + sub * 18432 + r * AP + c * 16;
        const __half* g = sub ? g_ql : g_qh;
        const char* src = (const char*)g +
            (baseE + (size_t)(q0 + r) * DD + c * 8) * 2;
        CP16(dst, src);
    }
    CP_COMMIT();
    CP_WAIT(0);
    __syncthreads();

    uint32_t qh[4][4], ql[4][4];
    #pragma unroll
    for (int ks = 0; ks < 4; ++ks) {
        uint32_t ra = (wm * 16 + a_r) * AP + a_cb + ks * 32;
        ldsm_x4(qh[ks][0], qh[ks][1], qh[ks][2], qh[ks][3], sb + 0 + ra);
        ldsm_x4(ql[ks][0], ql[ks][1], ql[ks][2], ql[ks][3], sb + 18432 + ra);
    }
    __syncthreads();

    float o[8][4];
    #pragma unroll
    for (int i = 0; i < 8; i++)
        #pragma unroll
        for (int j = 0; j < 4; j++) o[i][j] = 0.f;
    float lacc[4] = {0.f, 0.f, 0.f, 0.f};
    float m0 = -1e30f, m1 = -1e30f;

    const int row_min = q0 + wm * 16;
    const int r0g = row_min + (lid >> 2);
    const int col_e = (lid & 3) * 2;

    auto issue = [&](int j) {
        const uint32_t s0 = sb + (j % 3) * ABUF;
        #pragma unroll
        for (int p = 0; p < 6; ++p) {
            int idx = p * 256 + tid;      // 0..1535
            int sub = idx >> 9;           // 0 Kh, 1 Kl, 2 Vh
            int r   = (idx >> 3) & 63;
            int c   = idx & 7;
            const __half* g = (sub == 0) ? g_kh : (sub == 1) ? g_kl : g_vh;
            uint32_t dst = s0 + sub * ATILE + r * AP + c * 16;
            const char* src = (const char*)g +
                (baseE + (size_t)(j * 64 + r) * DD + c * 8) * 2;
            CP16(dst, src);
        }
        CP_COMMIT();
    };

    const int ntiles = 2 * qi + 2;        // >= 2 always
    issue(0);
    issue(1);

    for (int j = 0; j < ntiles; ++j) {
        if (j + 1 < ntiles) { CP_WAIT(1); } else { CP_WAIT(0); }
        __syncthreads();
        if (j + 2 < ntiles) issue(j + 2);

        const uint32_t bufb = sb + (j % 3) * ABUF;

        // ---- S = Q K^T (3-term fp16 split, term-major passes) ----
        float s[8][4];
        #pragma unroll
        for (int i = 0; i < 8; i++)
            #pragma unroll
            for (int q = 0; q < 4; q++) s[i][q] = 0.f;

        #pragma unroll
        for (int ks = 0; ks < 4; ++ks) {
            uint32_t bh[4][4], bl[4][4];
            #pragma unroll
            for (int ng = 0; ng < 4; ++ng) {
                uint32_t rb = (ng * 16 + b_r) * AP + b_cb + ks * 32;
                ldsm_x4(bh[ng][0], bh[ng][1], bh[ng][2], bh[ng][3], bufb + 0 * ATILE + rb);
                ldsm_x4(bl[ng][0], bl[ng][1], bl[ng][2], bl[ng][3], bufb + 1 * ATILE + rb);
            }
            #pragma unroll
            for (int nt = 0; nt < 8; ++nt)
                mma_f16(s[nt], qh[ks][0], qh[ks][1], qh[ks][2], qh[ks][3],
                        bh[nt >> 1][(nt & 1) * 2], bh[nt >> 1][(nt & 1) * 2 + 1]);
            #pragma unroll
            for (int nt = 0; nt < 8; ++nt)
                mma_f16(s[nt], qh[ks][0], qh[ks][1], qh[ks][2], qh[ks][3],
                        bl[nt >> 1][(nt & 1) * 2], bl[nt >> 1][(nt & 1) * 2 + 1]);
            #pragma unroll
            for (int nt = 0; nt < 8; ++nt)
                mma_f16(s[nt], ql[ks][0], ql[ks][1], ql[ks][2], ql[ks][3],
                        bh[nt >> 1][(nt & 1) * 2], bh[nt >> 1][(nt & 1) * 2 + 1]);
        }

        // ---- causal mask (S already scaled via Q) ----
        if (j * 64 + 63 > row_min) {
            #pragma unroll
            for (int nt = 0; nt < 8; ++nt) {
                int c0 = j * 64 + nt * 8 + col_e;
                if (c0     > r0g)     s[nt][0] = -1e30f;
                if (c0 + 1 > r0g)     s[nt][1] = -1e30f;
                if (c0     > r0g + 8) s[nt][2] = -1e30f;
                if (c0 + 1 > r0g + 8) s[nt][3] = -1e30f;
            }
        }

        // ---- online softmax (base-2, in fragments) ----
        float mx0 = -1e30f, mx1 = -1e30f;
        #pragma unroll
        for (int nt = 0; nt < 8; ++nt) {
            mx0 = fmaxf(mx0, fmaxf(s[nt][0], s[nt][1]));
            mx1 = fmaxf(mx1, fmaxf(s[nt][2], s[nt][3]));
        }
        mx0 = fmaxf(mx0, __shfl_xor_sync(0xffffffffu, mx0, 1));
        mx0 = fmaxf(mx0, __shfl_xor_sync(0xffffffffu, mx0, 2));
        mx1 = fmaxf(mx1, __shfl_xor_sync(0xffffffffu, mx1, 1));
        mx1 = fmaxf(mx1, __shfl_xor_sync(0xffffffffu, mx1, 2));
        float m0n = fmaxf(m0, mx0), m1n = fmaxf(m1, mx1);
        float f0 = exp2f(m0 - m0n), f1 = exp2f(m1 - m1n);
        m0 = m0n; m1 = m1n;

        #pragma unroll
        for (int nt = 0; nt < 8; ++nt) {
            s[nt][0] = exp2f(s[nt][0] - m0n);
            s[nt][1] = exp2f(s[nt][1] - m0n);
            s[nt][2] = exp2f(s[nt][2] - m1n);
            s[nt][3] = exp2f(s[nt][3] - m1n);
        }

        // rescale running accumulators (o and the MMA-computed row sums)
        #pragma unroll
        for (int nt = 0; nt < 8; ++nt) {
            o[nt][0] *= f0; o[nt][1] *= f0;
            o[nt][2] *= f1; o[nt][3] *= f1;
        }
        lacc[0] *= f0; lacc[1] *= f0; lacc[2] *= f1; lacc[3] *= f1;

        // ---- O += P V (1-term: P,V fp16 hi-only) + l row-sum via ones-MMA ----
        #pragma unroll
        for (int ks = 0; ks < 4; ++ks) {
            uint32_t pa[4];
            pa[0] = pack_h2(s[2*ks    ][0], s[2*ks    ][1]);
            pa[1] = pack_h2(s[2*ks    ][2], s[2*ks    ][3]);
            pa[2] = pack_h2(s[2*ks + 1][0], s[2*ks + 1][1]);
            pa[3] = pack_h2(s[2*ks + 1][2], s[2*ks + 1][3]);
            mma_f16(lacc, pa[0], pa[1], pa[2], pa[3], HONES, HONES);
            #pragma unroll
            for (int dg = 0; dg < 4; ++dg) {
                uint32_t vh[4];
                uint32_t rv = (ks * 16 + a_r) * AP + dg * 32 + a_cb;
                ldsm_x4_t(vh[0], vh[1], vh[2], vh[3], bufb + 2 * ATILE + rv);
                int nt = dg * 2;
                mma_f16(o[nt],     pa[0], pa[1], pa[2], pa[3], vh[0], vh[1]);
                mma_f16(o[nt + 1], pa[0], pa[1], pa[2], pa[3], vh[2], vh[3]);
            }
        }
        __syncthreads();
    }

    // ---- finalize: divide by l, write [B,T,C] fp32 ----
    {
        float inv0 = 1.0f / lacc[0], inv1 = 1.0f / lacc[2];
        #pragma unroll
        for (int nt = 0; nt < 8; ++nt) {
            int c = h * 64 + nt * 8 + col_e;
            float2 v0 = make_float2(o[nt][0] * inv0, o[nt][1] * inv0);
            float2 v1 = make_float2(o[nt][2] * inv1, o[nt][3] * inv1);
            *(float2*)(out + (size_t)(b * TT + r0g)     * CC + c) = v0;
            *(float2*)(out + (size_t)(b * TT + r0g + 8) * CC + c) = v1;
        }
    }
}

// ---------------------------------------------------------------------------
extern "C" void kernel_launch(void* const* d_in, const int* in_sizes, int n_in,
                              void* d_out, int out_size)
{
    const float* x    = (const float*)d_in[0];   // [2,2048,1024]
    const float* w    = (const float*)d_in[1];   // [1024,3072]
    const float* bias = (const float*)d_in[2];   // [3072]
    float* out = (float*)d_out;                  // [2,2048,1024]

    cudaFuncSetAttribute((const void*)qkv_gemm,
                         cudaFuncAttributeMaxDynamicSharedMemorySize, GEMM_SMEM);
    cudaFuncSetAttribute((const void*)attn_mma,
                         cudaFuncAttributeMaxDynamicSharedMemorySize, ATTN_SMEM);

    convert_x<<<MM * CC / 1024, 256>>>(x);
    convert_w<<<dim3(N3 / 128, CC / 16), 128>>>(w);
    qkv_gemm<<<dim3(N3 / 128, MM / 256), 512, GEMM_SMEM>>>(bias);
    attn_mma<<<dim3(TT / 128, HH, BB), 256, ATTN_SMEM>>>(out);
}